// round 4
// baseline (speedup 1.0000x reference)
#include <cuda_runtime.h>
#include <cuda_bf16.h>
#include <cstdint>

#define N_NODES 50000
#define IN_FEAT 256
#define NHEAD   4
#define DH      64
#define NREL    6
#define NEDGE   300000
#define OUTF    256   // NHEAD*DH
#define NEG_SLOPE 0.2f

// ---------------- scratch (device globals; no runtime allocation) ----------
__device__ float    g_feat[(size_t)NREL * N_NODES * OUTF];   // 307 MB
__device__ float    g_agg [(size_t)NREL * N_NODES * OUTF];   // 307 MB
__device__ float    g_el  [(size_t)NREL * N_NODES * NHEAD];
__device__ float    g_er  [(size_t)NREL * N_NODES * NHEAD];
__device__ unsigned g_mkey[(size_t)NREL * N_NODES * NHEAD];
__device__ float    g_z   [(size_t)NREL * N_NODES * NHEAD];
__device__ float    g_e   [(size_t)NREL * NEDGE   * NHEAD];  // scores, then a

// packed fp32x2 FMA (FFMA2) — only reachable via PTX on sm_103a
#define FMA2(d, a, b) \
    asm("fma.rn.f32x2 %0, %1, %2, %0;" : "+l"(d) : "l"(a), "l"(b))

#define RED4(ptr, vx, vy, vz, vw) \
    asm volatile("red.global.add.v4.f32 [%0], {%1, %2, %3, %4};" \
                 :: "l"(ptr), "f"(vx), "f"(vy), "f"(vz), "f"(vw) : "memory")

// monotone float<->uint encoding so atomicMax(uint) == float max
__device__ __forceinline__ unsigned enc_f(float f) {
    unsigned b = __float_as_uint(f);
    return (b & 0x80000000u) ? ~b : (b | 0x80000000u);
}
__device__ __forceinline__ float dec_f(unsigned k) {
    unsigned b = (k & 0x80000000u) ? (k ^ 0x80000000u) : ~k;
    return __uint_as_float(b);
}

// ---------------- 1. init --------------------------------------------------
__global__ void init_kernel() {
    size_t i      = (size_t)blockIdx.x * blockDim.x + threadIdx.x;
    size_t stride = (size_t)gridDim.x * blockDim.x;
    const size_t agg4 = (size_t)NREL * N_NODES * OUTF / 4;
    float4* a4 = reinterpret_cast<float4*>(g_agg);
    float4  zz = make_float4(0.f, 0.f, 0.f, 0.f);
    for (size_t j = i; j < agg4; j += stride) a4[j] = zz;
    const size_t nh = (size_t)NREL * N_NODES * NHEAD;
    for (size_t j = i; j < nh; j += stride) { g_z[j] = 0.f; g_mkey[j] = 0u; }
}

// ---------------- 2. batched GEMM  feat[r] = x @ W[r]  (FFMA2) -------------
#define BM 128
#define BN 128
#define BK 16
__global__ __launch_bounds__(256) void gemm_kernel(const float* __restrict__ x,
                                                   const float* __restrict__ W) {
    __shared__ float As[BK][BM];        // transposed x tile: As[k][row]
    __shared__ float Bs[BK][BN * 2];    // duplicated pairs: {b,b} per column

    const int r    = blockIdx.z;
    const int row0 = blockIdx.x * BM;
    const int col0 = blockIdx.y * BN;
    const float* Wr = W + (size_t)r * IN_FEAT * OUTF;
    float* C = g_feat + (size_t)r * N_NODES * OUTF;

    const int tid = threadIdx.x;
    const int tx  = tid & 15;       // 0..15 -> col block of 8
    const int ty  = tid >> 4;       // 0..15 -> row block of 8

    // acc[rp][c]: fp32x2 pair = rows (ty*8+2rp, ty*8+2rp+1), col tx*8+c
    unsigned long long acc[4][8];
#pragma unroll
    for (int i = 0; i < 4; i++)
#pragma unroll
        for (int j = 0; j < 8; j++) acc[i][j] = 0ull;

    for (int kt = 0; kt < IN_FEAT; kt += BK) {
        // load As: 128 rows x 16 k (512 float4 slots, 2 per thread), transposed
#pragma unroll
        for (int i = 0; i < 2; i++) {
            int slot = tid + i * 256;
            int rl   = slot >> 2;
            int c4   = slot & 3;
            int grow = row0 + rl;
            float4 v = make_float4(0.f, 0.f, 0.f, 0.f);
            if (grow < N_NODES)
                v = *reinterpret_cast<const float4*>(&x[(size_t)grow * IN_FEAT + kt + c4 * 4]);
            As[c4 * 4 + 0][rl] = v.x;
            As[c4 * 4 + 1][rl] = v.y;
            As[c4 * 4 + 2][rl] = v.z;
            As[c4 * 4 + 3][rl] = v.w;
        }
        // load Bs duplicated: 16 k x 128 cols (512 float4 loads, 2 per thread)
#pragma unroll
        for (int i = 0; i < 2; i++) {
            int slot = tid + i * 256;
            int rowk = slot >> 5;       // 0..15
            int c8   = slot & 31;       // 0..31 -> cols c8*4..c8*4+3
            float4 w = *reinterpret_cast<const float4*>(
                &Wr[(size_t)(kt + rowk) * OUTF + col0 + c8 * 4]);
            *reinterpret_cast<float4*>(&Bs[rowk][c8 * 8]) =
                make_float4(w.x, w.x, w.y, w.y);
            *reinterpret_cast<float4*>(&Bs[rowk][c8 * 8 + 4]) =
                make_float4(w.z, w.z, w.w, w.w);
        }
        __syncthreads();
#pragma unroll
        for (int k = 0; k < BK; k++) {
            ulonglong2 a01 = *reinterpret_cast<const ulonglong2*>(&As[k][ty * 8]);
            ulonglong2 a23 = *reinterpret_cast<const ulonglong2*>(&As[k][ty * 8 + 4]);
            unsigned long long av[4] = {a01.x, a01.y, a23.x, a23.y};
            ulonglong2 b01 = *reinterpret_cast<const ulonglong2*>(&Bs[k][tx * 16]);
            ulonglong2 b23 = *reinterpret_cast<const ulonglong2*>(&Bs[k][tx * 16 + 4]);
            ulonglong2 b45 = *reinterpret_cast<const ulonglong2*>(&Bs[k][tx * 16 + 8]);
            ulonglong2 b67 = *reinterpret_cast<const ulonglong2*>(&Bs[k][tx * 16 + 12]);
            unsigned long long bv[8] = {b01.x, b01.y, b23.x, b23.y,
                                        b45.x, b45.y, b67.x, b67.y};
#pragma unroll
            for (int rp = 0; rp < 4; rp++)
#pragma unroll
                for (int c = 0; c < 8; c++)
                    FMA2(acc[rp][c], av[rp], bv[c]);
        }
        __syncthreads();
    }

    // epilogue: unpack pairs, write 8 rows x 8 cols per thread
#pragma unroll
    for (int rp = 0; rp < 4; rp++) {
        float lo[8], hi[8];
#pragma unroll
        for (int c = 0; c < 8; c++)
            asm("mov.b64 {%0, %1}, %2;" : "=f"(lo[c]), "=f"(hi[c]) : "l"(acc[rp][c]));
        int gr0 = row0 + ty * 8 + rp * 2;
        if (gr0 < N_NODES) {
            float* cp = &C[(size_t)gr0 * OUTF + col0 + tx * 8];
            *reinterpret_cast<float4*>(cp)     = make_float4(lo[0], lo[1], lo[2], lo[3]);
            *reinterpret_cast<float4*>(cp + 4) = make_float4(lo[4], lo[5], lo[6], lo[7]);
        }
        if (gr0 + 1 < N_NODES) {
            float* cp = &C[(size_t)(gr0 + 1) * OUTF + col0 + tx * 8];
            *reinterpret_cast<float4*>(cp)     = make_float4(hi[0], hi[1], hi[2], hi[3]);
            *reinterpret_cast<float4*>(cp + 4) = make_float4(hi[4], hi[5], hi[6], hi[7]);
        }
    }
}

// ---------------- 3. attention dots el/er ----------------------------------
__global__ void attn_kernel(const float* __restrict__ attn_l,
                            const float* __restrict__ attn_r) {
    int gw   = (blockIdx.x * blockDim.x + threadIdx.x) >> 5;
    int lane = threadIdx.x & 31;
    const int total = NREL * N_NODES * NHEAD;
    if (gw >= total) return;
    int h = gw % NHEAD;
    int n = (gw / NHEAD) % N_NODES;
    int r = gw / (NHEAD * N_NODES);
    const float* f = g_feat + ((size_t)r * N_NODES + n) * OUTF + h * DH;
    const float* al = attn_l + (r * NHEAD + h) * DH;
    const float* ar = attn_r + (r * NHEAD + h) * DH;
    float v0 = f[lane], v1 = f[lane + 32];
    float sl = v0 * al[lane] + v1 * al[lane + 32];
    float sr = v0 * ar[lane] + v1 * ar[lane + 32];
#pragma unroll
    for (int o = 16; o > 0; o >>= 1) {
        sl += __shfl_xor_sync(0xffffffffu, sl, o);
        sr += __shfl_xor_sync(0xffffffffu, sr, o);
    }
    if (lane == 0) { g_el[gw] = sl; g_er[gw] = sr; }
}

// ---------------- 4. edge scores + segment max ------------------------------
__global__ void edge1_kernel(const int* __restrict__ src,
                             const int* __restrict__ dst) {
    int i = blockIdx.x * blockDim.x + threadIdx.x;
    if (i >= NREL * NEDGE) return;
    int r = i / NEDGE;
    int s = src[i];
    int d = dst[i];
    if ((unsigned)s >= N_NODES || (unsigned)d >= N_NODES) return; // defensive
    float4 l4 = *reinterpret_cast<const float4*>(&g_el[((size_t)r * N_NODES + s) * NHEAD]);
    float4 r4 = *reinterpret_cast<const float4*>(&g_er[((size_t)r * N_NODES + d) * NHEAD]);
    float ev[4] = {l4.x + r4.x, l4.y + r4.y, l4.z + r4.z, l4.w + r4.w};
#pragma unroll
    for (int h = 0; h < 4; h++) ev[h] = (ev[h] > 0.f) ? ev[h] : NEG_SLOPE * ev[h];
    *reinterpret_cast<float4*>(&g_e[(size_t)i * NHEAD]) =
        make_float4(ev[0], ev[1], ev[2], ev[3]);
    unsigned* mk = &g_mkey[((size_t)r * N_NODES + d) * NHEAD];
#pragma unroll
    for (int h = 0; h < 4; h++) atomicMax(&mk[h], enc_f(ev[h]));
}

// ---------------- 5. exp + segment sum --------------------------------------
__global__ void edge2_kernel(const int* __restrict__ dst) {
    int i = blockIdx.x * blockDim.x + threadIdx.x;
    if (i >= NREL * NEDGE) return;
    int r = i / NEDGE;
    int d = dst[i];
    if ((unsigned)d >= N_NODES) return; // defensive
    size_t nb = ((size_t)r * N_NODES + d) * NHEAD;
    float4 ev = *reinterpret_cast<const float4*>(&g_e[(size_t)i * NHEAD]);
    uint4  mk = *reinterpret_cast<const uint4*>(&g_mkey[nb]);
    float a0 = __expf(ev.x - dec_f(mk.x));
    float a1 = __expf(ev.y - dec_f(mk.y));
    float a2 = __expf(ev.z - dec_f(mk.z));
    float a3 = __expf(ev.w - dec_f(mk.w));
    *reinterpret_cast<float4*>(&g_e[(size_t)i * NHEAD]) = make_float4(a0, a1, a2, a3);
    atomicAdd(&g_z[nb + 0], a0);
    atomicAdd(&g_z[nb + 1], a1);
    atomicAdd(&g_z[nb + 2], a2);
    atomicAdd(&g_z[nb + 3], a3);
}

// ---------------- 6. weighted scatter (warp per edge, v4 reductions) --------
__global__ void edge3_kernel(const int* __restrict__ src,
                             const int* __restrict__ dst) {
    int gw   = (blockIdx.x * blockDim.x + threadIdx.x) >> 5;
    int lane = threadIdx.x & 31;
    if (gw >= NREL * NEDGE) return;
    int r = gw / NEDGE;
    int s = src[gw];
    int d = dst[gw];
    if ((unsigned)s >= N_NODES || (unsigned)d >= N_NODES) return; // defensive
    float4 a4 = *reinterpret_cast<const float4*>(&g_e[(size_t)gw * NHEAD]);
    float4 z4 = *reinterpret_cast<const float4*>(&g_z[((size_t)r * N_NODES + d) * NHEAD]);
    float alpha[4] = {a4.x / fmaxf(z4.x, 1e-9f), a4.y / fmaxf(z4.y, 1e-9f),
                      a4.z / fmaxf(z4.z, 1e-9f), a4.w / fmaxf(z4.w, 1e-9f)};
    const float4* fs = reinterpret_cast<const float4*>(
        &g_feat[((size_t)r * N_NODES + s) * OUTF]);
    float* ad = &g_agg[((size_t)r * N_NODES + d) * OUTF];
#pragma unroll
    for (int it = 0; it < 2; it++) {
        int c4 = lane + 32 * it;          // 0..63
        float4 f = fs[c4];
        float  al = alpha[c4 >> 4];
        RED4(ad + c4 * 4, al * f.x, al * f.y, al * f.z, al * f.w);
    }
}

// ---------------- 7. combine relations + final relu -------------------------
__global__ void final_kernel(const float* __restrict__ bias, float* __restrict__ out) {
    int i = blockIdx.x * blockDim.x + threadIdx.x;   // float4 index
    const int total4 = N_NODES * OUTF / 4;
    if (i >= total4) return;
    int c4 = i & 63;
    int n  = i >> 6;
    float4 acc = make_float4(0.f, 0.f, 0.f, 0.f);
#pragma unroll
    for (int r = 0; r < NREL; r++) {
        float4 g = *reinterpret_cast<const float4*>(
            &g_agg[((size_t)r * N_NODES + n) * OUTF + c4 * 4]);
        float4 b = *reinterpret_cast<const float4*>(&bias[r * OUTF + c4 * 4]);
        acc.x += fmaxf(g.x + b.x, 0.f);
        acc.y += fmaxf(g.y + b.y, 0.f);
        acc.z += fmaxf(g.z + b.z, 0.f);
        acc.w += fmaxf(g.w + b.w, 0.f);
    }
    acc.x = fmaxf(acc.x, 0.f);
    acc.y = fmaxf(acc.y, 0.f);
    acc.z = fmaxf(acc.z, 0.f);
    acc.w = fmaxf(acc.w, 0.f);
    reinterpret_cast<float4*>(out)[i] = acc;
}

// ---------------- launch -----------------------------------------------------
extern "C" void kernel_launch(void* const* d_in, const int* in_sizes, int n_in,
                              void* d_out, int out_size) {
    (void)in_sizes; (void)n_in; (void)out_size;
    const float* x      = (const float*)d_in[0];
    const float* W      = (const float*)d_in[1];
    const float* attn_l = (const float*)d_in[2];
    const float* attn_r = (const float*)d_in[3];
    const float* bias   = (const float*)d_in[4];
    const int*   src    = (const int*)d_in[5];
    const int*   dst    = (const int*)d_in[6];
    float*       out    = (float*)d_out;

    init_kernel<<<2048, 256>>>();

    dim3 gg((N_NODES + BM - 1) / BM, OUTF / BN, NREL);
    gemm_kernel<<<gg, 256>>>(x, W);

    {
        long long warps = (long long)NREL * N_NODES * NHEAD;
        int blocks = (int)((warps * 32 + 255) / 256);
        attn_kernel<<<blocks, 256>>>(attn_l, attn_r);
    }

    int ne = NREL * NEDGE;
    edge1_kernel<<<(ne + 255) / 256, 256>>>(src, dst);
    edge2_kernel<<<(ne + 255) / 256, 256>>>(dst);

    {
        long long thr = (long long)ne * 32;
        int blocks = (int)((thr + 255) / 256);
        edge3_kernel<<<blocks, 256>>>(src, dst);
    }

    final_kernel<<<(N_NODES * OUTF / 4 + 255) / 256, 256>>>(bias, out);
}

// round 5
// speedup vs baseline: 1.0035x; 1.0035x over previous
#include <cuda_runtime.h>
#include <cuda_bf16.h>
#include <cstdint>

#define N_NODES 50000
#define IN_FEAT 256
#define NHEAD   4
#define DH      64
#define NREL    6
#define NEDGE   300000
#define OUTF    256   // NHEAD*DH
#define NEG_SLOPE 0.2f

// ---------------- scratch (device globals; no runtime allocation) ----------
__device__ float    g_feat[(size_t)NREL * N_NODES * OUTF];   // 307 MB
__device__ float    g_agg [(size_t)NREL * N_NODES * OUTF];   // 307 MB
__device__ float    g_el  [(size_t)NREL * N_NODES * NHEAD];
__device__ float    g_er  [(size_t)NREL * N_NODES * NHEAD];
__device__ unsigned g_mkey[(size_t)NREL * N_NODES * NHEAD];
__device__ float    g_z   [(size_t)NREL * N_NODES * NHEAD];
__device__ float    g_e   [(size_t)NREL * NEDGE   * NHEAD];  // scores, then a

// packed fp32x2 FMA (FFMA2) — only reachable via PTX on sm_103a
#define FMA2(d, a, b) \
    asm("fma.rn.f32x2 %0, %1, %2, %0;" : "+l"(d) : "l"(a), "l"(b))

#define RED4(ptr, vx, vy, vz, vw) \
    asm volatile("red.global.add.v4.f32 [%0], {%1, %2, %3, %4};" \
                 :: "l"(ptr), "f"(vx), "f"(vy), "f"(vz), "f"(vw) : "memory")

// monotone float<->uint encoding so atomicMax(uint) == float max
__device__ __forceinline__ unsigned enc_f(float f) {
    unsigned b = __float_as_uint(f);
    return (b & 0x80000000u) ? ~b : (b | 0x80000000u);
}
__device__ __forceinline__ float dec_f(unsigned k) {
    unsigned b = (k & 0x80000000u) ? (k ^ 0x80000000u) : ~k;
    return __uint_as_float(b);
}

// ---------------- 1. init --------------------------------------------------
__global__ void init_kernel() {
    size_t i      = (size_t)blockIdx.x * blockDim.x + threadIdx.x;
    size_t stride = (size_t)gridDim.x * blockDim.x;
    const size_t agg4 = (size_t)NREL * N_NODES * OUTF / 4;
    float4* a4 = reinterpret_cast<float4*>(g_agg);
    float4  zz = make_float4(0.f, 0.f, 0.f, 0.f);
    for (size_t j = i; j < agg4; j += stride) a4[j] = zz;
    const size_t nh = (size_t)NREL * N_NODES * NHEAD;
    for (size_t j = i; j < nh; j += stride) { g_z[j] = 0.f; g_mkey[j] = 0u; }
}

// ---------------- 2. batched GEMM  feat[r] = x @ W[r]  (FFMA2) -------------
#define BM 128
#define BN 128
#define BK 16
__global__ __launch_bounds__(256) void gemm_kernel(const float* __restrict__ x,
                                                   const float* __restrict__ W) {
    __shared__ float As[BK][BM];        // transposed x tile: As[k][row]
    __shared__ float Bs[BK][BN * 2];    // duplicated pairs: {b,b} per column

    const int r    = blockIdx.z;
    const int row0 = blockIdx.x * BM;
    const int col0 = blockIdx.y * BN;
    const float* Wr = W + (size_t)r * IN_FEAT * OUTF;
    float* C = g_feat + (size_t)r * N_NODES * OUTF;

    const int tid = threadIdx.x;
    const int tx  = tid & 15;       // 0..15 -> col block of 8
    const int ty  = tid >> 4;       // 0..15 -> row block of 8

    // acc[rp][c]: fp32x2 pair = rows (ty*8+2rp, ty*8+2rp+1), col tx*8+c
    unsigned long long acc[4][8];
#pragma unroll
    for (int i = 0; i < 4; i++)
#pragma unroll
        for (int j = 0; j < 8; j++) acc[i][j] = 0ull;

    for (int kt = 0; kt < IN_FEAT; kt += BK) {
        // load As: 128 rows x 16 k (512 float4 slots, 2 per thread), transposed
#pragma unroll
        for (int i = 0; i < 2; i++) {
            int slot = tid + i * 256;
            int rl   = slot >> 2;
            int c4   = slot & 3;
            int grow = row0 + rl;
            float4 v = make_float4(0.f, 0.f, 0.f, 0.f);
            if (grow < N_NODES)
                v = *reinterpret_cast<const float4*>(&x[(size_t)grow * IN_FEAT + kt + c4 * 4]);
            As[c4 * 4 + 0][rl] = v.x;
            As[c4 * 4 + 1][rl] = v.y;
            As[c4 * 4 + 2][rl] = v.z;
            As[c4 * 4 + 3][rl] = v.w;
        }
        // load Bs duplicated: 16 k x 128 cols (512 float4 loads, 2 per thread)
#pragma unroll
        for (int i = 0; i < 2; i++) {
            int slot = tid + i * 256;
            int rowk = slot >> 5;       // 0..15
            int c8   = slot & 31;       // 0..31 -> cols c8*4..c8*4+3
            float4 w = *reinterpret_cast<const float4*>(
                &Wr[(size_t)(kt + rowk) * OUTF + col0 + c8 * 4]);
            *reinterpret_cast<float4*>(&Bs[rowk][c8 * 8]) =
                make_float4(w.x, w.x, w.y, w.y);
            *reinterpret_cast<float4*>(&Bs[rowk][c8 * 8 + 4]) =
                make_float4(w.z, w.z, w.w, w.w);
        }
        __syncthreads();
#pragma unroll
        for (int k = 0; k < BK; k++) {
            ulonglong2 a01 = *reinterpret_cast<const ulonglong2*>(&As[k][ty * 8]);
            ulonglong2 a23 = *reinterpret_cast<const ulonglong2*>(&As[k][ty * 8 + 4]);
            unsigned long long av[4] = {a01.x, a01.y, a23.x, a23.y};
            ulonglong2 b01 = *reinterpret_cast<const ulonglong2*>(&Bs[k][tx * 16]);
            ulonglong2 b23 = *reinterpret_cast<const ulonglong2*>(&Bs[k][tx * 16 + 4]);
            ulonglong2 b45 = *reinterpret_cast<const ulonglong2*>(&Bs[k][tx * 16 + 8]);
            ulonglong2 b67 = *reinterpret_cast<const ulonglong2*>(&Bs[k][tx * 16 + 12]);
            unsigned long long bv[8] = {b01.x, b01.y, b23.x, b23.y,
                                        b45.x, b45.y, b67.x, b67.y};
#pragma unroll
            for (int rp = 0; rp < 4; rp++)
#pragma unroll
                for (int c = 0; c < 8; c++)
                    FMA2(acc[rp][c], av[rp], bv[c]);
        }
        __syncthreads();
    }

    // epilogue: unpack pairs, write 8 rows x 8 cols per thread
#pragma unroll
    for (int rp = 0; rp < 4; rp++) {
        float lo[8], hi[8];
#pragma unroll
        for (int c = 0; c < 8; c++)
            asm("mov.b64 {%0, %1}, %2;" : "=f"(lo[c]), "=f"(hi[c]) : "l"(acc[rp][c]));
        int gr0 = row0 + ty * 8 + rp * 2;
        if (gr0 < N_NODES) {
            float* cp = &C[(size_t)gr0 * OUTF + col0 + tx * 8];
            *reinterpret_cast<float4*>(cp)     = make_float4(lo[0], lo[1], lo[2], lo[3]);
            *reinterpret_cast<float4*>(cp + 4) = make_float4(lo[4], lo[5], lo[6], lo[7]);
        }
        if (gr0 + 1 < N_NODES) {
            float* cp = &C[(size_t)(gr0 + 1) * OUTF + col0 + tx * 8];
            *reinterpret_cast<float4*>(cp)     = make_float4(hi[0], hi[1], hi[2], hi[3]);
            *reinterpret_cast<float4*>(cp + 4) = make_float4(hi[4], hi[5], hi[6], hi[7]);
        }
    }
}

// ---------------- 3. attention dots el/er ----------------------------------
__global__ void attn_kernel(const float* __restrict__ attn_l,
                            const float* __restrict__ attn_r) {
    int gw   = (blockIdx.x * blockDim.x + threadIdx.x) >> 5;
    int lane = threadIdx.x & 31;
    const int total = NREL * N_NODES * NHEAD;
    if (gw >= total) return;
    int h = gw % NHEAD;
    int n = (gw / NHEAD) % N_NODES;
    int r = gw / (NHEAD * N_NODES);
    const float* f = g_feat + ((size_t)r * N_NODES + n) * OUTF + h * DH;
    const float* al = attn_l + (r * NHEAD + h) * DH;
    const float* ar = attn_r + (r * NHEAD + h) * DH;
    float v0 = f[lane], v1 = f[lane + 32];
    float sl = v0 * al[lane] + v1 * al[lane + 32];
    float sr = v0 * ar[lane] + v1 * ar[lane + 32];
#pragma unroll
    for (int o = 16; o > 0; o >>= 1) {
        sl += __shfl_xor_sync(0xffffffffu, sl, o);
        sr += __shfl_xor_sync(0xffffffffu, sr, o);
    }
    if (lane == 0) { g_el[gw] = sl; g_er[gw] = sr; }
}

// ---------------- 4. edge scores + segment max ------------------------------
__global__ void edge1_kernel(const int* __restrict__ src,
                             const int* __restrict__ dst) {
    int i = blockIdx.x * blockDim.x + threadIdx.x;
    if (i >= NREL * NEDGE) return;
    int r = i / NEDGE;
    int s = src[i];
    int d = dst[i];
    if ((unsigned)s >= N_NODES || (unsigned)d >= N_NODES) return; // defensive
    float4 l4 = *reinterpret_cast<const float4*>(&g_el[((size_t)r * N_NODES + s) * NHEAD]);
    float4 r4 = *reinterpret_cast<const float4*>(&g_er[((size_t)r * N_NODES + d) * NHEAD]);
    float ev[4] = {l4.x + r4.x, l4.y + r4.y, l4.z + r4.z, l4.w + r4.w};
#pragma unroll
    for (int h = 0; h < 4; h++) ev[h] = (ev[h] > 0.f) ? ev[h] : NEG_SLOPE * ev[h];
    *reinterpret_cast<float4*>(&g_e[(size_t)i * NHEAD]) =
        make_float4(ev[0], ev[1], ev[2], ev[3]);
    unsigned* mk = &g_mkey[((size_t)r * N_NODES + d) * NHEAD];
#pragma unroll
    for (int h = 0; h < 4; h++) atomicMax(&mk[h], enc_f(ev[h]));
}

// ---------------- 5. exp + segment sum --------------------------------------
__global__ void edge2_kernel(const int* __restrict__ dst) {
    int i = blockIdx.x * blockDim.x + threadIdx.x;
    if (i >= NREL * NEDGE) return;
    int r = i / NEDGE;
    int d = dst[i];
    if ((unsigned)d >= N_NODES) return; // defensive
    size_t nb = ((size_t)r * N_NODES + d) * NHEAD;
    float4 ev = *reinterpret_cast<const float4*>(&g_e[(size_t)i * NHEAD]);
    uint4  mk = *reinterpret_cast<const uint4*>(&g_mkey[nb]);
    float a0 = __expf(ev.x - dec_f(mk.x));
    float a1 = __expf(ev.y - dec_f(mk.y));
    float a2 = __expf(ev.z - dec_f(mk.z));
    float a3 = __expf(ev.w - dec_f(mk.w));
    *reinterpret_cast<float4*>(&g_e[(size_t)i * NHEAD]) = make_float4(a0, a1, a2, a3);
    atomicAdd(&g_z[nb + 0], a0);
    atomicAdd(&g_z[nb + 1], a1);
    atomicAdd(&g_z[nb + 2], a2);
    atomicAdd(&g_z[nb + 3], a3);
}

// ---------------- 6. weighted scatter (warp per edge, v4 reductions) --------
__global__ void edge3_kernel(const int* __restrict__ src,
                             const int* __restrict__ dst) {
    int gw   = (blockIdx.x * blockDim.x + threadIdx.x) >> 5;
    int lane = threadIdx.x & 31;
    if (gw >= NREL * NEDGE) return;
    int r = gw / NEDGE;
    int s = src[gw];
    int d = dst[gw];
    if ((unsigned)s >= N_NODES || (unsigned)d >= N_NODES) return; // defensive
    float4 a4 = *reinterpret_cast<const float4*>(&g_e[(size_t)gw * NHEAD]);
    float4 z4 = *reinterpret_cast<const float4*>(&g_z[((size_t)r * N_NODES + d) * NHEAD]);
    float alpha[4] = {a4.x / fmaxf(z4.x, 1e-9f), a4.y / fmaxf(z4.y, 1e-9f),
                      a4.z / fmaxf(z4.z, 1e-9f), a4.w / fmaxf(z4.w, 1e-9f)};
    const float4* fs = reinterpret_cast<const float4*>(
        &g_feat[((size_t)r * N_NODES + s) * OUTF]);
    float* ad = &g_agg[((size_t)r * N_NODES + d) * OUTF];
#pragma unroll
    for (int it = 0; it < 2; it++) {
        int c4 = lane + 32 * it;          // 0..63
        float4 f = fs[c4];
        float  al = alpha[c4 >> 4];
        RED4(ad + c4 * 4, al * f.x, al * f.y, al * f.z, al * f.w);
    }
}

// ---------------- 7. combine relations + final relu -------------------------
__global__ void final_kernel(const float* __restrict__ bias, float* __restrict__ out) {
    int i = blockIdx.x * blockDim.x + threadIdx.x;   // float4 index
    const int total4 = N_NODES * OUTF / 4;
    if (i >= total4) return;
    int c4 = i & 63;
    int n  = i >> 6;
    float4 acc = make_float4(0.f, 0.f, 0.f, 0.f);
#pragma unroll
    for (int r = 0; r < NREL; r++) {
        float4 g = *reinterpret_cast<const float4*>(
            &g_agg[((size_t)r * N_NODES + n) * OUTF + c4 * 4]);
        float4 b = *reinterpret_cast<const float4*>(&bias[r * OUTF + c4 * 4]);
        acc.x += fmaxf(g.x + b.x, 0.f);
        acc.y += fmaxf(g.y + b.y, 0.f);
        acc.z += fmaxf(g.z + b.z, 0.f);
        acc.w += fmaxf(g.w + b.w, 0.f);
    }
    acc.x = fmaxf(acc.x, 0.f);
    acc.y = fmaxf(acc.y, 0.f);
    acc.z = fmaxf(acc.z, 0.f);
    acc.w = fmaxf(acc.w, 0.f);
    reinterpret_cast<float4*>(out)[i] = acc;
}

// ---------------- launch -----------------------------------------------------
extern "C" void kernel_launch(void* const* d_in, const int* in_sizes, int n_in,
                              void* d_out, int out_size) {
    (void)in_sizes; (void)n_in; (void)out_size;
    const float* x      = (const float*)d_in[0];
    const float* W      = (const float*)d_in[1];
    const float* attn_l = (const float*)d_in[2];
    const float* attn_r = (const float*)d_in[3];
    const float* bias   = (const float*)d_in[4];
    const int*   src    = (const int*)d_in[5];
    const int*   dst    = (const int*)d_in[6];
    float*       out    = (float*)d_out;

    init_kernel<<<2048, 256>>>();

    dim3 gg((N_NODES + BM - 1) / BM, OUTF / BN, NREL);
    gemm_kernel<<<gg, 256>>>(x, W);

    {
        long long warps = (long long)NREL * N_NODES * NHEAD;
        int blocks = (int)((warps * 32 + 255) / 256);
        attn_kernel<<<blocks, 256>>>(attn_l, attn_r);
    }

    int ne = NREL * NEDGE;
    edge1_kernel<<<(ne + 255) / 256, 256>>>(src, dst);
    edge2_kernel<<<(ne + 255) / 256, 256>>>(dst);

    {
        long long thr = (long long)ne * 32;
        int blocks = (int)((thr + 255) / 256);
        edge3_kernel<<<blocks, 256>>>(src, dst);
    }

    final_kernel<<<(N_NODES * OUTF / 4 + 255) / 256, 256>>>(bias, out);
}

// round 7
// speedup vs baseline: 1.3775x; 1.3728x over previous
#include <cuda_runtime.h>
#include <cuda_bf16.h>
#include <cstdint>

#define N_NODES 50000
#define IN_FEAT 256
#define NHEAD   4
#define DH      64
#define NREL    6
#define NEDGE   300000
#define OUTF    256   // NHEAD*DH
#define NEG_SLOPE 0.2f

// ---------------- scratch (device globals; no runtime allocation) ----------
__device__ float    g_feat[(size_t)NREL * N_NODES * OUTF];   // 307 MB
__device__ float    g_agg [(size_t)NREL * N_NODES * OUTF];   // 307 MB
__device__ float    g_el  [(size_t)NREL * N_NODES * NHEAD];
__device__ float    g_er  [(size_t)NREL * N_NODES * NHEAD];
__device__ unsigned g_mkey[(size_t)NREL * N_NODES * NHEAD];
__device__ float    g_z   [(size_t)NREL * N_NODES * NHEAD];
__device__ float    g_e   [(size_t)NREL * NEDGE   * NHEAD];  // scores, then a

// packed fp32x2 FMA (FFMA2) — only reachable via PTX on sm_103a
#define FMA2(d, a, b) \
    asm("fma.rn.f32x2 %0, %1, %2, %0;" : "+l"(d) : "l"(a), "l"(b))

// monotone float<->uint encoding so atomicMax(uint) == float max
__device__ __forceinline__ unsigned enc_f(float f) {
    unsigned b = __float_as_uint(f);
    return (b & 0x80000000u) ? ~b : (b | 0x80000000u);
}
__device__ __forceinline__ float dec_f(unsigned k) {
    unsigned b = (k & 0x80000000u) ? (k ^ 0x80000000u) : ~k;
    return __uint_as_float(b);
}

// ---------------- 1. init --------------------------------------------------
__global__ void init_kernel() {
    size_t i      = (size_t)blockIdx.x * blockDim.x + threadIdx.x;
    size_t stride = (size_t)gridDim.x * blockDim.x;
    const size_t agg4 = (size_t)NREL * N_NODES * OUTF / 4;
    float4* a4 = reinterpret_cast<float4*>(g_agg);
    float4  zz = make_float4(0.f, 0.f, 0.f, 0.f);
    for (size_t j = i; j < agg4; j += stride) a4[j] = zz;
    const size_t nh = (size_t)NREL * N_NODES * NHEAD;
    for (size_t j = i; j < nh; j += stride) { g_z[j] = 0.f; g_mkey[j] = 0u; }
}

// ---------------- 2. batched GEMM  feat[r] = x @ W[r]  (FFMA2, BN=64) -------
#define BM 128
#define BN 64
#define BK 16
__global__ __launch_bounds__(256) void gemm_kernel(const float* __restrict__ x,
                                                   const float* __restrict__ W) {
    __shared__ float As[BK][BM];        // transposed x tile: As[k][row]
    __shared__ float Bs[BK][BN * 2];    // duplicated pairs: Bs[k][2c],Bs[k][2c+1] = W[k][c]

    const int r    = blockIdx.z;
    const int row0 = blockIdx.x * BM;
    const int col0 = blockIdx.y * BN;
    const float* Wr = W + (size_t)r * IN_FEAT * OUTF;
    float* C = g_feat + (size_t)r * N_NODES * OUTF;

    const int tid = threadIdx.x;
    const int tx  = tid & 15;       // cols: tx, tx+16, tx+32, tx+48
    const int ty  = tid >> 4;       // rows: ty*8 .. ty*8+7 (4 packed pairs)

    // acc[rp][c]: f32x2 = rows (ty*8+2rp, ty*8+2rp+1), col = tx + 16c
    unsigned long long acc[4][4];
#pragma unroll
    for (int i = 0; i < 4; i++)
#pragma unroll
        for (int j = 0; j < 4; j++) acc[i][j] = 0ull;

    for (int kt = 0; kt < IN_FEAT; kt += BK) {
        // load As: 128 rows x 16 k (512 float4 slots, 2 per thread), transposed
#pragma unroll
        for (int i = 0; i < 2; i++) {
            int slot = tid + i * 256;
            int rl   = slot >> 2;
            int c4   = slot & 3;
            int grow = row0 + rl;
            float4 v = make_float4(0.f, 0.f, 0.f, 0.f);
            if (grow < N_NODES)
                v = *reinterpret_cast<const float4*>(&x[(size_t)grow * IN_FEAT + kt + c4 * 4]);
            As[c4 * 4 + 0][rl] = v.x;
            As[c4 * 4 + 1][rl] = v.y;
            As[c4 * 4 + 2][rl] = v.z;
            As[c4 * 4 + 3][rl] = v.w;
        }
        // load Bs duplicated: 16 k x 64 cols (256 float4 loads, 1 per thread)
        {
            int rowk = tid >> 4;        // 0..15
            int c4b  = tid & 15;        // cols c4b*4 .. c4b*4+3
            float4 w = *reinterpret_cast<const float4*>(
                &Wr[(size_t)(kt + rowk) * OUTF + col0 + c4b * 4]);
            *reinterpret_cast<float4*>(&Bs[rowk][c4b * 8]) =
                make_float4(w.x, w.x, w.y, w.y);
            *reinterpret_cast<float4*>(&Bs[rowk][c4b * 8 + 4]) =
                make_float4(w.z, w.z, w.w, w.w);
        }
        __syncthreads();
#pragma unroll
        for (int k = 0; k < BK; k++) {
            ulonglong2 a01 = *reinterpret_cast<const ulonglong2*>(&As[k][ty * 8]);
            ulonglong2 a23 = *reinterpret_cast<const ulonglong2*>(&As[k][ty * 8 + 4]);
            unsigned long long av[4] = {a01.x, a01.y, a23.x, a23.y};
            unsigned long long bv[4];
#pragma unroll
            for (int c = 0; c < 4; c++)
                bv[c] = *reinterpret_cast<const unsigned long long*>(
                    &Bs[k][(tx + 16 * c) * 2]);
#pragma unroll
            for (int rp = 0; rp < 4; rp++)
#pragma unroll
                for (int c = 0; c < 4; c++)
                    FMA2(acc[rp][c], av[rp], bv[c]);
        }
        __syncthreads();
    }

    // epilogue: unpack pairs; rows ty*8+2rp (lo) and +1 (hi), cols tx+16c
#pragma unroll
    for (int rp = 0; rp < 4; rp++) {
        float lo[4], hi[4];
#pragma unroll
        for (int c = 0; c < 4; c++)
            asm("mov.b64 {%0, %1}, %2;" : "=f"(lo[c]), "=f"(hi[c]) : "l"(acc[rp][c]));
        int gr0 = row0 + ty * 8 + rp * 2;
        if (gr0 < N_NODES) {
            float* cp = &C[(size_t)gr0 * OUTF + col0];
#pragma unroll
            for (int c = 0; c < 4; c++) cp[tx + 16 * c] = lo[c];
        }
        if (gr0 + 1 < N_NODES) {
            float* cp = &C[(size_t)(gr0 + 1) * OUTF + col0];
#pragma unroll
            for (int c = 0; c < 4; c++) cp[tx + 16 * c] = hi[c];
        }
    }
}

// ---------------- 3. attention dots el/er ----------------------------------
__global__ void attn_kernel(const float* __restrict__ attn_l,
                            const float* __restrict__ attn_r) {
    int gw   = (blockIdx.x * blockDim.x + threadIdx.x) >> 5;
    int lane = threadIdx.x & 31;
    const int total = NREL * N_NODES * NHEAD;
    if (gw >= total) return;
    int h = gw % NHEAD;
    int n = (gw / NHEAD) % N_NODES;
    int r = gw / (NHEAD * N_NODES);
    const float* f = g_feat + ((size_t)r * N_NODES + n) * OUTF + h * DH;
    const float* al = attn_l + (r * NHEAD + h) * DH;
    const float* ar = attn_r + (r * NHEAD + h) * DH;
    float v0 = f[lane], v1 = f[lane + 32];
    float sl = v0 * al[lane] + v1 * al[lane + 32];
    float sr = v0 * ar[lane] + v1 * ar[lane + 32];
#pragma unroll
    for (int o = 16; o > 0; o >>= 1) {
        sl += __shfl_xor_sync(0xffffffffu, sl, o);
        sr += __shfl_xor_sync(0xffffffffu, sr, o);
    }
    if (lane == 0) { g_el[gw] = sl; g_er[gw] = sr; }
}

// ---------------- 4. edge scores + segment max ------------------------------
__global__ void edge1_kernel(const int* __restrict__ src,
                             const int* __restrict__ dst) {
    int i = blockIdx.x * blockDim.x + threadIdx.x;
    if (i >= NREL * NEDGE) return;
    int r = i / NEDGE;
    int s = src[i];
    int d = dst[i];
    if ((unsigned)s >= N_NODES || (unsigned)d >= N_NODES) return; // defensive
    float4 l4 = *reinterpret_cast<const float4*>(&g_el[((size_t)r * N_NODES + s) * NHEAD]);
    float4 r4 = *reinterpret_cast<const float4*>(&g_er[((size_t)r * N_NODES + d) * NHEAD]);
    float ev[4] = {l4.x + r4.x, l4.y + r4.y, l4.z + r4.z, l4.w + r4.w};
#pragma unroll
    for (int h = 0; h < 4; h++) ev[h] = (ev[h] > 0.f) ? ev[h] : NEG_SLOPE * ev[h];
    *reinterpret_cast<float4*>(&g_e[(size_t)i * NHEAD]) =
        make_float4(ev[0], ev[1], ev[2], ev[3]);
    unsigned* mk = &g_mkey[((size_t)r * N_NODES + d) * NHEAD];
#pragma unroll
    for (int h = 0; h < 4; h++) atomicMax(&mk[h], enc_f(ev[h]));
}

// ---------------- 5. exp + segment sum --------------------------------------
__global__ void edge2_kernel(const int* __restrict__ dst) {
    int i = blockIdx.x * blockDim.x + threadIdx.x;
    if (i >= NREL * NEDGE) return;
    int r = i / NEDGE;
    int d = dst[i];
    if ((unsigned)d >= N_NODES) return; // defensive
    size_t nb = ((size_t)r * N_NODES + d) * NHEAD;
    float4 ev = *reinterpret_cast<const float4*>(&g_e[(size_t)i * NHEAD]);
    uint4  mk = *reinterpret_cast<const uint4*>(&g_mkey[nb]);
    float a0 = __expf(ev.x - dec_f(mk.x));
    float a1 = __expf(ev.y - dec_f(mk.y));
    float a2 = __expf(ev.z - dec_f(mk.z));
    float a3 = __expf(ev.w - dec_f(mk.w));
    *reinterpret_cast<float4*>(&g_e[(size_t)i * NHEAD]) = make_float4(a0, a1, a2, a3);
    atomicAdd(&g_z[nb + 0], a0);
    atomicAdd(&g_z[nb + 1], a1);
    atomicAdd(&g_z[nb + 2], a2);
    atomicAdd(&g_z[nb + 3], a3);
}

// ---------------- 6. weighted scatter (warp per edge) -----------------------
__global__ void edge3_kernel(const int* __restrict__ src,
                             const int* __restrict__ dst) {
    int gw   = (blockIdx.x * blockDim.x + threadIdx.x) >> 5;
    int lane = threadIdx.x & 31;
    if (gw >= NREL * NEDGE) return;
    int r = gw / NEDGE;
    int s = src[gw];
    int d = dst[gw];
    if ((unsigned)s >= N_NODES || (unsigned)d >= N_NODES) return; // defensive
    float4 a4 = *reinterpret_cast<const float4*>(&g_e[(size_t)gw * NHEAD]);
    float4 z4 = *reinterpret_cast<const float4*>(&g_z[((size_t)r * N_NODES + d) * NHEAD]);
    float alpha[4] = {a4.x / fmaxf(z4.x, 1e-9f), a4.y / fmaxf(z4.y, 1e-9f),
                      a4.z / fmaxf(z4.z, 1e-9f), a4.w / fmaxf(z4.w, 1e-9f)};
    const float4* fs = reinterpret_cast<const float4*>(
        &g_feat[((size_t)r * N_NODES + s) * OUTF]);
    float* ad = &g_agg[((size_t)r * N_NODES + d) * OUTF];
#pragma unroll
    for (int it = 0; it < 2; it++) {
        int c4 = lane + 32 * it;          // 0..63
        float4 f = fs[c4];
        float  al = alpha[c4 >> 4];
        int    c  = c4 * 4;
        atomicAdd(ad + c + 0, al * f.x);
        atomicAdd(ad + c + 1, al * f.y);
        atomicAdd(ad + c + 2, al * f.z);
        atomicAdd(ad + c + 3, al * f.w);
    }
}

// ---------------- 7. combine relations + final relu -------------------------
__global__ void final_kernel(const float* __restrict__ bias, float* __restrict__ out) {
    int i = blockIdx.x * blockDim.x + threadIdx.x;   // float4 index
    const int total4 = N_NODES * OUTF / 4;
    if (i >= total4) return;
    int c4 = i & 63;
    int n  = i >> 6;
    float4 acc = make_float4(0.f, 0.f, 0.f, 0.f);
#pragma unroll
    for (int r = 0; r < NREL; r++) {
        float4 g = *reinterpret_cast<const float4*>(
            &g_agg[((size_t)r * N_NODES + n) * OUTF + c4 * 4]);
        float4 b = *reinterpret_cast<const float4*>(&bias[r * OUTF + c4 * 4]);
        acc.x += fmaxf(g.x + b.x, 0.f);
        acc.y += fmaxf(g.y + b.y, 0.f);
        acc.z += fmaxf(g.z + b.z, 0.f);
        acc.w += fmaxf(g.w + b.w, 0.f);
    }
    acc.x = fmaxf(acc.x, 0.f);
    acc.y = fmaxf(acc.y, 0.f);
    acc.z = fmaxf(acc.z, 0.f);
    acc.w = fmaxf(acc.w, 0.f);
    reinterpret_cast<float4*>(out)[i] = acc;
}

// ---------------- launch -----------------------------------------------------
extern "C" void kernel_launch(void* const* d_in, const int* in_sizes, int n_in,
                              void* d_out, int out_size) {
    (void)in_sizes; (void)n_in; (void)out_size;
    const float* x      = (const float*)d_in[0];
    const float* W      = (const float*)d_in[1];
    const float* attn_l = (const float*)d_in[2];
    const float* attn_r = (const float*)d_in[3];
    const float* bias   = (const float*)d_in[4];
    const int*   src    = (const int*)d_in[5];
    const int*   dst    = (const int*)d_in[6];
    float*       out    = (float*)d_out;

    init_kernel<<<2048, 256>>>();

    dim3 gg((N_NODES + BM - 1) / BM, OUTF / BN, NREL);
    gemm_kernel<<<gg, 256>>>(x, W);

    {
        long long warps = (long long)NREL * N_NODES * NHEAD;
        int blocks = (int)((warps * 32 + 255) / 256);
        attn_kernel<<<blocks, 256>>>(attn_l, attn_r);
    }

    int ne = NREL * NEDGE;
    edge1_kernel<<<(ne + 255) / 256, 256>>>(src, dst);
    edge2_kernel<<<(ne + 255) / 256, 256>>>(dst);

    {
        long long thr = (long long)ne * 32;
        int blocks = (int)((thr + 255) / 256);
        edge3_kernel<<<blocks, 256>>>(src, dst);
    }

    final_kernel<<<(N_NODES * OUTF / 4 + 255) / 256, 256>>>(bias, out);
}

// round 13
// speedup vs baseline: 1.7739x; 1.2877x over previous
#include <cuda_runtime.h>
#include <cuda_bf16.h>
#include <mma.h>
#include <cstdint>

using namespace nvcuda;

#define N_NODES 50000
#define IN_FEAT 256
#define NHEAD   4
#define DH      64
#define NREL    6
#define NEDGE   300000
#define OUTF    256   // NHEAD*DH
#define NEG_SLOPE 0.2f

// ---------------- scratch (device globals; no runtime allocation) ----------
__device__ float         g_feat[(size_t)NREL * N_NODES * OUTF];   // 307 MB
__device__ float         g_agg [(size_t)NREL * N_NODES * OUTF];   // 307 MB
__device__ __nv_bfloat16 g_xbh [(size_t)N_NODES * IN_FEAT];       // bf16 hi of x
__device__ __nv_bfloat16 g_xbl [(size_t)N_NODES * IN_FEAT];       // bf16 lo of x
__device__ __nv_bfloat16 g_wbh [(size_t)NREL * OUTF * IN_FEAT];   // W^T hi [r][n][k]
__device__ __nv_bfloat16 g_wbl [(size_t)NREL * OUTF * IN_FEAT];   // W^T lo
__device__ float         g_el  [(size_t)NREL * N_NODES * NHEAD];
__device__ float         g_er  [(size_t)NREL * N_NODES * NHEAD];
__device__ unsigned      g_mkey[(size_t)NREL * N_NODES * NHEAD];
__device__ float         g_z   [(size_t)NREL * N_NODES * NHEAD];
__device__ float         g_e   [(size_t)NREL * NEDGE   * NHEAD];  // scores, then a

// monotone float<->uint encoding so atomicMax(uint) == float max
__device__ __forceinline__ unsigned enc_f(float f) {
    unsigned b = __float_as_uint(f);
    return (b & 0x80000000u) ? ~b : (b | 0x80000000u);
}
__device__ __forceinline__ float dec_f(unsigned k) {
    unsigned b = (k & 0x80000000u) ? (k ^ 0x80000000u) : ~k;
    return __uint_as_float(b);
}

// ---------------- 1. init --------------------------------------------------
__global__ void init_kernel() {
    size_t i      = (size_t)blockIdx.x * blockDim.x + threadIdx.x;
    size_t stride = (size_t)gridDim.x * blockDim.x;
    const size_t agg4 = (size_t)NREL * N_NODES * OUTF / 4;
    float4* a4 = reinterpret_cast<float4*>(g_agg);
    float4  zz = make_float4(0.f, 0.f, 0.f, 0.f);
    for (size_t j = i; j < agg4; j += stride) a4[j] = zz;
    const size_t nh = (size_t)NREL * N_NODES * NHEAD;
    for (size_t j = i; j < nh; j += stride) { g_z[j] = 0.f; g_mkey[j] = 0u; }
}

// ---------------- 1b. split x into bf16 hi/lo -------------------------------
__global__ void split_x_kernel(const float* __restrict__ x) {
    int i = blockIdx.x * blockDim.x + threadIdx.x;     // float4 index
    const int total4 = N_NODES * IN_FEAT / 4;
    if (i >= total4) return;
    float4 v = reinterpret_cast<const float4*>(x)[i];
    __nv_bfloat16 h[4], l[4];
    float vv[4] = {v.x, v.y, v.z, v.w};
#pragma unroll
    for (int j = 0; j < 4; j++) {
        h[j] = __float2bfloat16(vv[j]);
        l[j] = __float2bfloat16(vv[j] - __bfloat162float(h[j]));
    }
    *reinterpret_cast<uint2*>(&g_xbh[(size_t)i * 4]) = *reinterpret_cast<uint2*>(h);
    *reinterpret_cast<uint2*>(&g_xbl[(size_t)i * 4]) = *reinterpret_cast<uint2*>(l);
}

// ---------------- 1c. transpose + split W into bf16 hi/lo -------------------
__global__ void split_w_kernel(const float* __restrict__ W) {
    int i = blockIdx.x * blockDim.x + threadIdx.x;     // over NREL*256*256
    if (i >= NREL * IN_FEAT * OUTF) return;
    int n = i & 255;
    int k = (i >> 8) & 255;
    int r = i >> 16;
    float w = W[((size_t)r * IN_FEAT + k) * OUTF + n];
    __nv_bfloat16 h = __float2bfloat16(w);
    __nv_bfloat16 l = __float2bfloat16(w - __bfloat162float(h));
    size_t o = ((size_t)r * OUTF + n) * IN_FEAT + k;
    g_wbh[o] = h;
    g_wbl[o] = l;
}

// ---------------- 2. tensor GEMM via wmma (bf16 split, 3 mma) ---------------
// CTA: 128x128, BK=32. 8 warps as 2(m) x 4(n); warp tile 64x32 = 4x2 wmma tiles.
#define GBM 128
#define GBN 128
#define GBK 32
#define SSTRIDE 40   // smem row stride in bf16 elements (pad vs conflicts)

__global__ __launch_bounds__(256) void gemm_wmma_kernel() {
    __shared__ __nv_bfloat16 Ah[GBM * SSTRIDE];
    __shared__ __nv_bfloat16 Al[GBM * SSTRIDE];
    __shared__ __nv_bfloat16 Bh[GBN * SSTRIDE];
    __shared__ __nv_bfloat16 Bl[GBN * SSTRIDE];

    const int tid  = threadIdx.x;
    const int wid  = tid >> 5;
    const int lane = tid & 31;
    const int wm   = wid >> 2;          // 0..1
    const int wn   = wid & 3;           // 0..3
    const int r    = blockIdx.z;
    const int row0 = blockIdx.x * GBM;
    const int col0 = blockIdx.y * GBN;

    const __nv_bfloat16* wbh = g_wbh + (size_t)r * OUTF * IN_FEAT;
    const __nv_bfloat16* wbl = g_wbl + (size_t)r * OUTF * IN_FEAT;

    wmma::fragment<wmma::accumulator, 16, 16, 16, float> acc[4][2];
#pragma unroll
    for (int mt = 0; mt < 4; mt++)
#pragma unroll
        for (int nt = 0; nt < 2; nt++) wmma::fill_fragment(acc[mt][nt], 0.0f);

    for (int kt = 0; kt < IN_FEAT; kt += GBK) {
        // ---- global -> smem: A hi/lo (128 rows x 32 k)
        // 512 slots of 8 bf16 (uint4 = 16B = 8 elems), 2 slots per thread
#pragma unroll
        for (int it = 0; it < 2; it++) {
            int slot = tid + it * 256;   // 0..511
            int m    = slot >> 2;        // 0..127
            int k8   = slot & 3;         // 0..3 -> k = k8*8 .. k8*8+7
            int grow = row0 + m;
            uint4 vh = make_uint4(0u, 0u, 0u, 0u), vl = vh;
            if (grow < N_NODES) {
                size_t go = (size_t)grow * IN_FEAT + kt + k8 * 8;
                vh = *reinterpret_cast<const uint4*>(&g_xbh[go]);
                vl = *reinterpret_cast<const uint4*>(&g_xbl[go]);
            }
            *reinterpret_cast<uint4*>(&Ah[m * SSTRIDE + k8 * 8]) = vh;
            *reinterpret_cast<uint4*>(&Al[m * SSTRIDE + k8 * 8]) = vl;
        }
        // ---- global -> smem: B hi/lo (128 n-rows x 32 k) ----
#pragma unroll
        for (int it = 0; it < 2; it++) {
            int slot = tid + it * 256;
            int n    = slot >> 2;
            int k8   = slot & 3;
            size_t go = (size_t)(col0 + n) * IN_FEAT + kt + k8 * 8;
            uint4 vh = *reinterpret_cast<const uint4*>(&wbh[go]);
            uint4 vl = *reinterpret_cast<const uint4*>(&wbl[go]);
            *reinterpret_cast<uint4*>(&Bh[n * SSTRIDE + k8 * 8]) = vh;
            *reinterpret_cast<uint4*>(&Bl[n * SSTRIDE + k8 * 8]) = vl;
        }
        __syncthreads();

#pragma unroll
        for (int k16 = 0; k16 < GBK; k16 += 16) {
            wmma::fragment<wmma::matrix_b, 16, 16, 16, __nv_bfloat16,
                           wmma::col_major> b_h[2], b_l[2];
#pragma unroll
            for (int nt = 0; nt < 2; nt++) {
                wmma::load_matrix_sync(b_h[nt], &Bh[(wn * 32 + nt * 16) * SSTRIDE + k16], SSTRIDE);
                wmma::load_matrix_sync(b_l[nt], &Bl[(wn * 32 + nt * 16) * SSTRIDE + k16], SSTRIDE);
            }
#pragma unroll
            for (int mt = 0; mt < 4; mt++) {
                wmma::fragment<wmma::matrix_a, 16, 16, 16, __nv_bfloat16,
                               wmma::row_major> a_h, a_l;
                wmma::load_matrix_sync(a_h, &Ah[(wm * 64 + mt * 16) * SSTRIDE + k16], SSTRIDE);
                wmma::load_matrix_sync(a_l, &Al[(wm * 64 + mt * 16) * SSTRIDE + k16], SSTRIDE);
#pragma unroll
                for (int nt = 0; nt < 2; nt++) {
                    wmma::mma_sync(acc[mt][nt], a_h, b_h[nt], acc[mt][nt]);
                    wmma::mma_sync(acc[mt][nt], a_h, b_l[nt], acc[mt][nt]);
                    wmma::mma_sync(acc[mt][nt], a_l, b_h[nt], acc[mt][nt]);
                }
            }
        }
        __syncthreads();
    }

    // ---- epilogue ----
    float* C = g_feat + (size_t)r * N_NODES * OUTF;
    if (row0 + GBM <= N_NODES) {
#pragma unroll
        for (int mt = 0; mt < 4; mt++)
#pragma unroll
            for (int nt = 0; nt < 2; nt++) {
                int row = row0 + wm * 64 + mt * 16;
                int col = col0 + wn * 32 + nt * 16;
                wmma::store_matrix_sync(&C[(size_t)row * OUTF + col],
                                        acc[mt][nt], OUTF, wmma::mem_row_major);
            }
    } else {
        // boundary block: bounce through smem with row guards (ldm=16).
        float* scr = reinterpret_cast<float*>(Ah) + wid * 256;   // 16x16 per warp
#pragma unroll
        for (int mt = 0; mt < 4; mt++)
#pragma unroll
            for (int nt = 0; nt < 2; nt++) {
                wmma::store_matrix_sync(scr, acc[mt][nt], 16, wmma::mem_row_major);
                __syncwarp();
                int rr = lane >> 1;
                int cc = (lane & 1) * 8;
                int grow = row0 + wm * 64 + mt * 16 + rr;
                if (grow < N_NODES) {
                    float* cp = &C[(size_t)grow * OUTF + col0 + wn * 32 + nt * 16 + cc];
                    const float* sp = &scr[rr * 16 + cc];
#pragma unroll
                    for (int j = 0; j < 8; j++) cp[j] = sp[j];
                }
                __syncwarp();
            }
    }
}

// ---------------- 3. attention dots el/er ----------------------------------
__global__ void attn_kernel(const float* __restrict__ attn_l,
                            const float* __restrict__ attn_r) {
    int gw   = (blockIdx.x * blockDim.x + threadIdx.x) >> 5;
    int lane = threadIdx.x & 31;
    const int total = NREL * N_NODES * NHEAD;
    if (gw >= total) return;
    int h = gw % NHEAD;
    int n = (gw / NHEAD) % N_NODES;
    int r = gw / (NHEAD * N_NODES);
    const float* f = g_feat + ((size_t)r * N_NODES + n) * OUTF + h * DH;
    const float* al = attn_l + (r * NHEAD + h) * DH;
    const float* ar = attn_r + (r * NHEAD + h) * DH;
    float v0 = f[lane], v1 = f[lane + 32];
    float sl = v0 * al[lane] + v1 * al[lane + 32];
    float sr = v0 * ar[lane] + v1 * ar[lane + 32];
#pragma unroll
    for (int o = 16; o > 0; o >>= 1) {
        sl += __shfl_xor_sync(0xffffffffu, sl, o);
        sr += __shfl_xor_sync(0xffffffffu, sr, o);
    }
    if (lane == 0) { g_el[gw] = sl; g_er[gw] = sr; }
}

// ---------------- 4. edge scores + segment max ------------------------------
__global__ void edge1_kernel(const int* __restrict__ src,
                             const int* __restrict__ dst) {
    int i = blockIdx.x * blockDim.x + threadIdx.x;
    if (i >= NREL * NEDGE) return;
    int r = i / NEDGE;
    int s = src[i];
    int d = dst[i];
    if ((unsigned)s >= N_NODES || (unsigned)d >= N_NODES) return; // defensive
    float4 l4 = *reinterpret_cast<const float4*>(&g_el[((size_t)r * N_NODES + s) * NHEAD]);
    float4 r4 = *reinterpret_cast<const float4*>(&g_er[((size_t)r * N_NODES + d) * NHEAD]);
    float ev[4] = {l4.x + r4.x, l4.y + r4.y, l4.z + r4.z, l4.w + r4.w};
#pragma unroll
    for (int h = 0; h < 4; h++) ev[h] = (ev[h] > 0.f) ? ev[h] : NEG_SLOPE * ev[h];
    *reinterpret_cast<float4*>(&g_e[(size_t)i * NHEAD]) =
        make_float4(ev[0], ev[1], ev[2], ev[3]);
    unsigned* mk = &g_mkey[((size_t)r * N_NODES + d) * NHEAD];
#pragma unroll
    for (int h = 0; h < 4; h++) atomicMax(&mk[h], enc_f(ev[h]));
}

// ---------------- 5. exp + segment sum --------------------------------------
__global__ void edge2_kernel(const int* __restrict__ dst) {
    int i = blockIdx.x * blockDim.x + threadIdx.x;
    if (i >= NREL * NEDGE) return;
    int r = i / NEDGE;
    int d = dst[i];
    if ((unsigned)d >= N_NODES) return; // defensive
    size_t nb = ((size_t)r * N_NODES + d) * NHEAD;
    float4 ev = *reinterpret_cast<const float4*>(&g_e[(size_t)i * NHEAD]);
    uint4  mk = *reinterpret_cast<const uint4*>(&g_mkey[nb]);
    float a0 = __expf(ev.x - dec_f(mk.x));
    float a1 = __expf(ev.y - dec_f(mk.y));
    float a2 = __expf(ev.z - dec_f(mk.z));
    float a3 = __expf(ev.w - dec_f(mk.w));
    *reinterpret_cast<float4*>(&g_e[(size_t)i * NHEAD]) = make_float4(a0, a1, a2, a3);
    atomicAdd(&g_z[nb + 0], a0);
    atomicAdd(&g_z[nb + 1], a1);
    atomicAdd(&g_z[nb + 2], a2);
    atomicAdd(&g_z[nb + 3], a3);
}

// ---------------- 6. weighted scatter (warp per edge) -----------------------
__global__ void edge3_kernel(const int* __restrict__ src,
                             const int* __restrict__ dst) {
    int gw   = (blockIdx.x * blockDim.x + threadIdx.x) >> 5;
    int lane = threadIdx.x & 31;
    if (gw >= NREL * NEDGE) return;
    int r = gw / NEDGE;
    int s = src[gw];
    int d = dst[gw];
    if ((unsigned)s >= N_NODES || (unsigned)d >= N_NODES) return; // defensive
    float4 a4 = *reinterpret_cast<const float4*>(&g_e[(size_t)gw * NHEAD]);
    float4 z4 = *reinterpret_cast<const float4*>(&g_z[((size_t)r * N_NODES + d) * NHEAD]);
    float alpha[4] = {a4.x / fmaxf(z4.x, 1e-9f), a4.y / fmaxf(z4.y, 1e-9f),
                      a4.z / fmaxf(z4.z, 1e-9f), a4.w / fmaxf(z4.w, 1e-9f)};
    const float4* fs = reinterpret_cast<const float4*>(
        &g_feat[((size_t)r * N_NODES + s) * OUTF]);
    float* ad = &g_agg[((size_t)r * N_NODES + d) * OUTF];
#pragma unroll
    for (int it = 0; it < 2; it++) {
        int c4 = lane + 32 * it;          // 0..63
        float4 f = fs[c4];
        float  al = alpha[c4 >> 4];
        int    c  = c4 * 4;
        atomicAdd(ad + c + 0, al * f.x);
        atomicAdd(ad + c + 1, al * f.y);
        atomicAdd(ad + c + 2, al * f.z);
        atomicAdd(ad + c + 3, al * f.w);
    }
}

// ---------------- 7. combine relations + final relu -------------------------
__global__ void final_kernel(const float* __restrict__ bias, float* __restrict__ out) {
    int i = blockIdx.x * blockDim.x + threadIdx.x;   // float4 index
    const int total4 = N_NODES * OUTF / 4;
    if (i >= total4) return;
    int c4 = i & 63;
    int n  = i >> 6;
    float4 acc = make_float4(0.f, 0.f, 0.f, 0.f);
#pragma unroll
    for (int r = 0; r < NREL; r++) {
        float4 g = *reinterpret_cast<const float4*>(
            &g_agg[((size_t)r * N_NODES + n) * OUTF + c4 * 4]);
        float4 b = *reinterpret_cast<const float4*>(&bias[r * OUTF + c4 * 4]);
        acc.x += fmaxf(g.x + b.x, 0.f);
        acc.y += fmaxf(g.y + b.y, 0.f);
        acc.z += fmaxf(g.z + b.z, 0.f);
        acc.w += fmaxf(g.w + b.w, 0.f);
    }
    acc.x = fmaxf(acc.x, 0.f);
    acc.y = fmaxf(acc.y, 0.f);
    acc.z = fmaxf(acc.z, 0.f);
    acc.w = fmaxf(acc.w, 0.f);
    reinterpret_cast<float4*>(out)[i] = acc;
}

// ---------------- launch -----------------------------------------------------
extern "C" void kernel_launch(void* const* d_in, const int* in_sizes, int n_in,
                              void* d_out, int out_size) {
    (void)in_sizes; (void)n_in; (void)out_size;
    const float* x      = (const float*)d_in[0];
    const float* W      = (const float*)d_in[1];
    const float* attn_l = (const float*)d_in[2];
    const float* attn_r = (const float*)d_in[3];
    const float* bias   = (const float*)d_in[4];
    const int*   src    = (const int*)d_in[5];
    const int*   dst    = (const int*)d_in[6];
    float*       out    = (float*)d_out;

    init_kernel<<<2048, 256>>>();
    split_x_kernel<<<(N_NODES * IN_FEAT / 4 + 255) / 256, 256>>>(x);
    split_w_kernel<<<(NREL * IN_FEAT * OUTF + 255) / 256, 256>>>(W);

    dim3 gg((N_NODES + GBM - 1) / GBM, OUTF / GBN, NREL);
    gemm_wmma_kernel<<<gg, 256>>>();

    {
        long long warps = (long long)NREL * N_NODES * NHEAD;
        int blocks = (int)((warps * 32 + 255) / 256);
        attn_kernel<<<blocks, 256>>>(attn_l, attn_r);
    }

    int ne = NREL * NEDGE;
    edge1_kernel<<<(ne + 255) / 256, 256>>>(src, dst);
    edge2_kernel<<<(ne + 255) / 256, 256>>>(dst);

    {
        long long thr = (long long)ne * 32;
        int blocks = (int)((thr + 255) / 256);
        edge3_kernel<<<blocks, 256>>>(src, dst);
    }

    final_kernel<<<(N_NODES * OUTF / 4 + 255) / 256, 256>>>(bias, out);
}

// round 15
// speedup vs baseline: 2.6623x; 1.5008x over previous
#include <cuda_runtime.h>
#include <cuda_bf16.h>
#include <mma.h>
#include <cstdint>

using namespace nvcuda;

#define N_NODES 50000
#define IN_FEAT 256
#define NHEAD   4
#define DH      64
#define NREL    6
#define NEDGE   300000
#define OUTF    256   // NHEAD*DH
#define NEG_SLOPE 0.2f

// ---------------- scratch (device globals; no runtime allocation) ----------
__device__ float         g_feat[(size_t)NREL * N_NODES * OUTF];   // 307 MB
__device__ float         g_agg [(size_t)NREL * N_NODES * OUTF];   // 307 MB
__device__ __nv_bfloat16 g_xbh [(size_t)N_NODES * IN_FEAT];       // bf16 hi of x
__device__ __nv_bfloat16 g_xbl [(size_t)N_NODES * IN_FEAT];       // bf16 lo of x
__device__ __nv_bfloat16 g_wbh [(size_t)NREL * OUTF * IN_FEAT];   // W^T hi [r][n][k]
__device__ __nv_bfloat16 g_wbl [(size_t)NREL * OUTF * IN_FEAT];   // W^T lo
__device__ float         g_el  [(size_t)NREL * N_NODES * NHEAD];
__device__ float         g_er  [(size_t)NREL * N_NODES * NHEAD];
__device__ unsigned      g_mkey[(size_t)NREL * N_NODES * NHEAD];
__device__ float         g_z   [(size_t)NREL * N_NODES * NHEAD];
__device__ float         g_e   [(size_t)NREL * NEDGE   * NHEAD];  // scores, then a

// vector fp32 reduction to global (4x fewer L2 atomic ops than scalar)
#define RED4(ptr, vx, vy, vz, vw) \
    asm volatile("red.global.add.v4.f32 [%0], {%1, %2, %3, %4};" \
                 :: "l"(ptr), "f"(vx), "f"(vy), "f"(vz), "f"(vw) : "memory")

// monotone float<->uint encoding so atomicMax(uint) == float max
__device__ __forceinline__ unsigned enc_f(float f) {
    unsigned b = __float_as_uint(f);
    return (b & 0x80000000u) ? ~b : (b | 0x80000000u);
}
__device__ __forceinline__ float dec_f(unsigned k) {
    unsigned b = (k & 0x80000000u) ? (k ^ 0x80000000u) : ~k;
    return __uint_as_float(b);
}

// ---------------- 1. init --------------------------------------------------
__global__ void init_kernel() {
    size_t i      = (size_t)blockIdx.x * blockDim.x + threadIdx.x;
    size_t stride = (size_t)gridDim.x * blockDim.x;
    const size_t agg4 = (size_t)NREL * N_NODES * OUTF / 4;
    float4* a4 = reinterpret_cast<float4*>(g_agg);
    float4  zz = make_float4(0.f, 0.f, 0.f, 0.f);
    for (size_t j = i; j < agg4; j += stride) a4[j] = zz;
    const size_t nh = (size_t)NREL * N_NODES * NHEAD;
    for (size_t j = i; j < nh; j += stride) { g_z[j] = 0.f; g_mkey[j] = 0u; }
}

// ---------------- 1b. split x into bf16 hi/lo -------------------------------
__global__ void split_x_kernel(const float* __restrict__ x) {
    int i = blockIdx.x * blockDim.x + threadIdx.x;     // float4 index
    const int total4 = N_NODES * IN_FEAT / 4;
    if (i >= total4) return;
    float4 v = reinterpret_cast<const float4*>(x)[i];
    __nv_bfloat16 h[4], l[4];
    float vv[4] = {v.x, v.y, v.z, v.w};
#pragma unroll
    for (int j = 0; j < 4; j++) {
        h[j] = __float2bfloat16(vv[j]);
        l[j] = __float2bfloat16(vv[j] - __bfloat162float(h[j]));
    }
    *reinterpret_cast<uint2*>(&g_xbh[(size_t)i * 4]) = *reinterpret_cast<uint2*>(h);
    *reinterpret_cast<uint2*>(&g_xbl[(size_t)i * 4]) = *reinterpret_cast<uint2*>(l);
}

// ---------------- 1c. transpose + split W into bf16 hi/lo -------------------
__global__ void split_w_kernel(const float* __restrict__ W) {
    int i = blockIdx.x * blockDim.x + threadIdx.x;     // over NREL*256*256
    if (i >= NREL * IN_FEAT * OUTF) return;
    int n = i & 255;
    int k = (i >> 8) & 255;
    int r = i >> 16;
    float w = W[((size_t)r * IN_FEAT + k) * OUTF + n];
    __nv_bfloat16 h = __float2bfloat16(w);
    __nv_bfloat16 l = __float2bfloat16(w - __bfloat162float(h));
    size_t o = ((size_t)r * OUTF + n) * IN_FEAT + k;
    g_wbh[o] = h;
    g_wbl[o] = l;
}

// ---------------- 2. tensor GEMM via wmma (bf16 split, 3 mma) ---------------
// CTA: 128x128, BK=32. 8 warps as 2(m) x 4(n); warp tile 64x32 = 4x2 wmma tiles.
#define GBM 128
#define GBN 128
#define GBK 32
#define SSTRIDE 40   // smem row stride in bf16 elements (pad vs conflicts)

__global__ __launch_bounds__(256, 2) void gemm_wmma_kernel() {
    __shared__ __nv_bfloat16 Ah[GBM * SSTRIDE];
    __shared__ __nv_bfloat16 Al[GBM * SSTRIDE];
    __shared__ __nv_bfloat16 Bh[GBN * SSTRIDE];
    __shared__ __nv_bfloat16 Bl[GBN * SSTRIDE];

    const int tid  = threadIdx.x;
    const int wid  = tid >> 5;
    const int lane = tid & 31;
    const int wm   = wid >> 2;          // 0..1
    const int wn   = wid & 3;           // 0..3
    const int r    = blockIdx.z;
    const int row0 = blockIdx.x * GBM;
    const int col0 = blockIdx.y * GBN;

    const __nv_bfloat16* wbh = g_wbh + (size_t)r * OUTF * IN_FEAT;
    const __nv_bfloat16* wbl = g_wbl + (size_t)r * OUTF * IN_FEAT;

    wmma::fragment<wmma::accumulator, 16, 16, 16, float> acc[4][2];
#pragma unroll
    for (int mt = 0; mt < 4; mt++)
#pragma unroll
        for (int nt = 0; nt < 2; nt++) wmma::fill_fragment(acc[mt][nt], 0.0f);

    for (int kt = 0; kt < IN_FEAT; kt += GBK) {
        // ---- global -> smem: A hi/lo (128 rows x 32 k)
        // 512 slots of 8 bf16 (uint4 = 16B = 8 elems), 2 slots per thread
#pragma unroll
        for (int it = 0; it < 2; it++) {
            int slot = tid + it * 256;   // 0..511
            int m    = slot >> 2;        // 0..127
            int k8   = slot & 3;         // 0..3 -> k = k8*8 .. k8*8+7
            int grow = row0 + m;
            uint4 vh = make_uint4(0u, 0u, 0u, 0u), vl = vh;
            if (grow < N_NODES) {
                size_t go = (size_t)grow * IN_FEAT + kt + k8 * 8;
                vh = *reinterpret_cast<const uint4*>(&g_xbh[go]);
                vl = *reinterpret_cast<const uint4*>(&g_xbl[go]);
            }
            *reinterpret_cast<uint4*>(&Ah[m * SSTRIDE + k8 * 8]) = vh;
            *reinterpret_cast<uint4*>(&Al[m * SSTRIDE + k8 * 8]) = vl;
        }
        // ---- global -> smem: B hi/lo (128 n-rows x 32 k) ----
#pragma unroll
        for (int it = 0; it < 2; it++) {
            int slot = tid + it * 256;
            int n    = slot >> 2;
            int k8   = slot & 3;
            size_t go = (size_t)(col0 + n) * IN_FEAT + kt + k8 * 8;
            uint4 vh = *reinterpret_cast<const uint4*>(&wbh[go]);
            uint4 vl = *reinterpret_cast<const uint4*>(&wbl[go]);
            *reinterpret_cast<uint4*>(&Bh[n * SSTRIDE + k8 * 8]) = vh;
            *reinterpret_cast<uint4*>(&Bl[n * SSTRIDE + k8 * 8]) = vl;
        }
        __syncthreads();

#pragma unroll
        for (int k16 = 0; k16 < GBK; k16 += 16) {
            wmma::fragment<wmma::matrix_b, 16, 16, 16, __nv_bfloat16,
                           wmma::col_major> b_h[2], b_l[2];
#pragma unroll
            for (int nt = 0; nt < 2; nt++) {
                wmma::load_matrix_sync(b_h[nt], &Bh[(wn * 32 + nt * 16) * SSTRIDE + k16], SSTRIDE);
                wmma::load_matrix_sync(b_l[nt], &Bl[(wn * 32 + nt * 16) * SSTRIDE + k16], SSTRIDE);
            }
#pragma unroll
            for (int mt = 0; mt < 4; mt++) {
                wmma::fragment<wmma::matrix_a, 16, 16, 16, __nv_bfloat16,
                               wmma::row_major> a_h, a_l;
                wmma::load_matrix_sync(a_h, &Ah[(wm * 64 + mt * 16) * SSTRIDE + k16], SSTRIDE);
                wmma::load_matrix_sync(a_l, &Al[(wm * 64 + mt * 16) * SSTRIDE + k16], SSTRIDE);
#pragma unroll
                for (int nt = 0; nt < 2; nt++) {
                    wmma::mma_sync(acc[mt][nt], a_h, b_h[nt], acc[mt][nt]);
                    wmma::mma_sync(acc[mt][nt], a_h, b_l[nt], acc[mt][nt]);
                    wmma::mma_sync(acc[mt][nt], a_l, b_h[nt], acc[mt][nt]);
                }
            }
        }
        __syncthreads();
    }

    // ---- epilogue ----
    float* C = g_feat + (size_t)r * N_NODES * OUTF;
    if (row0 + GBM <= N_NODES) {
#pragma unroll
        for (int mt = 0; mt < 4; mt++)
#pragma unroll
            for (int nt = 0; nt < 2; nt++) {
                int row = row0 + wm * 64 + mt * 16;
                int col = col0 + wn * 32 + nt * 16;
                wmma::store_matrix_sync(&C[(size_t)row * OUTF + col],
                                        acc[mt][nt], OUTF, wmma::mem_row_major);
            }
    } else {
        // boundary block: bounce through smem with row guards (ldm=16).
        float* scr = reinterpret_cast<float*>(Ah) + wid * 256;   // 16x16 per warp
#pragma unroll
        for (int mt = 0; mt < 4; mt++)
#pragma unroll
            for (int nt = 0; nt < 2; nt++) {
                wmma::store_matrix_sync(scr, acc[mt][nt], 16, wmma::mem_row_major);
                __syncwarp();
                int rr = lane >> 1;
                int cc = (lane & 1) * 8;
                int grow = row0 + wm * 64 + mt * 16 + rr;
                if (grow < N_NODES) {
                    float* cp = &C[(size_t)grow * OUTF + col0 + wn * 32 + nt * 16 + cc];
                    const float* sp = &scr[rr * 16 + cc];
#pragma unroll
                    for (int j = 0; j < 8; j++) cp[j] = sp[j];
                }
                __syncwarp();
            }
    }
}

// ---------------- 3. attention dots el/er ----------------------------------
__global__ void attn_kernel(const float* __restrict__ attn_l,
                            const float* __restrict__ attn_r) {
    int gw   = (blockIdx.x * blockDim.x + threadIdx.x) >> 5;
    int lane = threadIdx.x & 31;
    const int total = NREL * N_NODES * NHEAD;
    if (gw >= total) return;
    int h = gw % NHEAD;
    int n = (gw / NHEAD) % N_NODES;
    int r = gw / (NHEAD * N_NODES);
    const float* f = g_feat + ((size_t)r * N_NODES + n) * OUTF + h * DH;
    const float* al = attn_l + (r * NHEAD + h) * DH;
    const float* ar = attn_r + (r * NHEAD + h) * DH;
    float v0 = f[lane], v1 = f[lane + 32];
    float sl = v0 * al[lane] + v1 * al[lane + 32];
    float sr = v0 * ar[lane] + v1 * ar[lane + 32];
#pragma unroll
    for (int o = 16; o > 0; o >>= 1) {
        sl += __shfl_xor_sync(0xffffffffu, sl, o);
        sr += __shfl_xor_sync(0xffffffffu, sr, o);
    }
    if (lane == 0) { g_el[gw] = sl; g_er[gw] = sr; }
}

// ---------------- 4. edge scores + segment max ------------------------------
__global__ void edge1_kernel(const int* __restrict__ src,
                             const int* __restrict__ dst) {
    int i = blockIdx.x * blockDim.x + threadIdx.x;
    if (i >= NREL * NEDGE) return;
    int r = i / NEDGE;
    int s = src[i];
    int d = dst[i];
    if ((unsigned)s >= N_NODES || (unsigned)d >= N_NODES) return; // defensive
    float4 l4 = *reinterpret_cast<const float4*>(&g_el[((size_t)r * N_NODES + s) * NHEAD]);
    float4 r4 = *reinterpret_cast<const float4*>(&g_er[((size_t)r * N_NODES + d) * NHEAD]);
    float ev[4] = {l4.x + r4.x, l4.y + r4.y, l4.z + r4.z, l4.w + r4.w};
#pragma unroll
    for (int h = 0; h < 4; h++) ev[h] = (ev[h] > 0.f) ? ev[h] : NEG_SLOPE * ev[h];
    *reinterpret_cast<float4*>(&g_e[(size_t)i * NHEAD]) =
        make_float4(ev[0], ev[1], ev[2], ev[3]);
    unsigned* mk = &g_mkey[((size_t)r * N_NODES + d) * NHEAD];
#pragma unroll
    for (int h = 0; h < 4; h++) atomicMax(&mk[h], enc_f(ev[h]));
}

// ---------------- 5. exp + segment sum --------------------------------------
__global__ void edge2_kernel(const int* __restrict__ dst) {
    int i = blockIdx.x * blockDim.x + threadIdx.x;
    if (i >= NREL * NEDGE) return;
    int r = i / NEDGE;
    int d = dst[i];
    if ((unsigned)d >= N_NODES) return; // defensive
    size_t nb = ((size_t)r * N_NODES + d) * NHEAD;
    float4 ev = *reinterpret_cast<const float4*>(&g_e[(size_t)i * NHEAD]);
    uint4  mk = *reinterpret_cast<const uint4*>(&g_mkey[nb]);
    float a0 = __expf(ev.x - dec_f(mk.x));
    float a1 = __expf(ev.y - dec_f(mk.y));
    float a2 = __expf(ev.z - dec_f(mk.z));
    float a3 = __expf(ev.w - dec_f(mk.w));
    *reinterpret_cast<float4*>(&g_e[(size_t)i * NHEAD]) = make_float4(a0, a1, a2, a3);
    atomicAdd(&g_z[nb + 0], a0);
    atomicAdd(&g_z[nb + 1], a1);
    atomicAdd(&g_z[nb + 2], a2);
    atomicAdd(&g_z[nb + 3], a3);
}

// ---------------- 6. weighted scatter (warp per edge, v4 reductions) --------
__global__ void edge3_kernel(const int* __restrict__ src,
                             const int* __restrict__ dst) {
    int gw   = (blockIdx.x * blockDim.x + threadIdx.x) >> 5;
    int lane = threadIdx.x & 31;
    if (gw >= NREL * NEDGE) return;
    int r = gw / NEDGE;
    int s = src[gw];
    int d = dst[gw];
    if ((unsigned)s >= N_NODES || (unsigned)d >= N_NODES) return; // defensive
    float4 a4 = *reinterpret_cast<const float4*>(&g_e[(size_t)gw * NHEAD]);
    float4 z4 = *reinterpret_cast<const float4*>(&g_z[((size_t)r * N_NODES + d) * NHEAD]);
    float alpha[4] = {a4.x / fmaxf(z4.x, 1e-9f), a4.y / fmaxf(z4.y, 1e-9f),
                      a4.z / fmaxf(z4.z, 1e-9f), a4.w / fmaxf(z4.w, 1e-9f)};
    const float4* fs = reinterpret_cast<const float4*>(
        &g_feat[((size_t)r * N_NODES + s) * OUTF]);
    float* ad = &g_agg[((size_t)r * N_NODES + d) * OUTF];
#pragma unroll
    for (int it = 0; it < 2; it++) {
        int c4 = lane + 32 * it;          // 0..63
        float4 f = fs[c4];
        float  al = alpha[c4 >> 4];
        RED4(ad + c4 * 4, al * f.x, al * f.y, al * f.z, al * f.w);
    }
}

// ---------------- 7. combine relations + final relu -------------------------
__global__ void final_kernel(const float* __restrict__ bias, float* __restrict__ out) {
    int i = blockIdx.x * blockDim.x + threadIdx.x;   // float4 index
    const int total4 = N_NODES * OUTF / 4;
    if (i >= total4) return;
    int c4 = i & 63;
    int n  = i >> 6;
    float4 acc = make_float4(0.f, 0.f, 0.f, 0.f);
#pragma unroll
    for (int r = 0; r < NREL; r++) {
        float4 g = *reinterpret_cast<const float4*>(
            &g_agg[((size_t)r * N_NODES + n) * OUTF + c4 * 4]);
        float4 b = *reinterpret_cast<const float4*>(&bias[r * OUTF + c4 * 4]);
        acc.x += fmaxf(g.x + b.x, 0.f);
        acc.y += fmaxf(g.y + b.y, 0.f);
        acc.z += fmaxf(g.z + b.z, 0.f);
        acc.w += fmaxf(g.w + b.w, 0.f);
    }
    acc.x = fmaxf(acc.x, 0.f);
    acc.y = fmaxf(acc.y, 0.f);
    acc.z = fmaxf(acc.z, 0.f);
    acc.w = fmaxf(acc.w, 0.f);
    reinterpret_cast<float4*>(out)[i] = acc;
}

// ---------------- launch -----------------------------------------------------
extern "C" void kernel_launch(void* const* d_in, const int* in_sizes, int n_in,
                              void* d_out, int out_size) {
    (void)in_sizes; (void)n_in; (void)out_size;
    const float* x      = (const float*)d_in[0];
    const float* W      = (const float*)d_in[1];
    const float* attn_l = (const float*)d_in[2];
    const float* attn_r = (const float*)d_in[3];
    const float* bias   = (const float*)d_in[4];
    const int*   src    = (const int*)d_in[5];
    const int*   dst    = (const int*)d_in[6];
    float*       out    = (float*)d_out;

    init_kernel<<<2048, 256>>>();
    split_x_kernel<<<(N_NODES * IN_FEAT / 4 + 255) / 256, 256>>>(x);
    split_w_kernel<<<(NREL * IN_FEAT * OUTF + 255) / 256, 256>>>(W);

    dim3 gg((N_NODES + GBM - 1) / GBM, OUTF / GBN, NREL);
    gemm_wmma_kernel<<<gg, 256>>>();

    {
        long long warps = (long long)NREL * N_NODES * NHEAD;
        int blocks = (int)((warps * 32 + 255) / 256);
        attn_kernel<<<blocks, 256>>>(attn_l, attn_r);
    }

    int ne = NREL * NEDGE;
    edge1_kernel<<<(ne + 255) / 256, 256>>>(src, dst);
    edge2_kernel<<<(ne + 255) / 256, 256>>>(dst);

    {
        long long thr = (long long)ne * 32;
        int blocks = (int)((thr + 255) / 256);
        edge3_kernel<<<blocks, 256>>>(src, dst);
    }

    final_kernel<<<(N_NODES * OUTF / 4 + 255) / 256, 256>>>(bias, out);
}

// round 17
// speedup vs baseline: 3.1761x; 1.1930x over previous
#include <cuda_runtime.h>
#include <cuda_bf16.h>
#include <mma.h>
#include <cstdint>

using namespace nvcuda;

#define N_NODES 50000
#define IN_FEAT 256
#define NHEAD   4
#define DH      64
#define NREL    6
#define NEDGE   300000
#define OUTF    256   // NHEAD*DH
#define NEG_SLOPE 0.2f

#define NKEY   (NREL * N_NODES)            // 300000 (r,dst) segments
#define NBLK   ((NKEY + 1023) / 1024)      // 293 scan blocks
#define NE_TOT (NREL * NEDGE)              // 1.8M edges

// ---------------- scratch (device globals; no runtime allocation) ----------
__device__ float         g_feat[(size_t)NREL * N_NODES * OUTF];   // 307 MB
__device__ float         g_agg [(size_t)NREL * N_NODES * OUTF];   // 307 MB
__device__ __nv_bfloat16 g_xbh [(size_t)N_NODES * IN_FEAT];
__device__ __nv_bfloat16 g_xbl [(size_t)N_NODES * IN_FEAT];
__device__ __nv_bfloat16 g_wbh [(size_t)NREL * OUTF * IN_FEAT];
__device__ __nv_bfloat16 g_wbl [(size_t)NREL * OUTF * IN_FEAT];
__device__ float         g_el  [(size_t)NREL * N_NODES * NHEAD];
__device__ float         g_er  [(size_t)NREL * N_NODES * NHEAD];
__device__ unsigned      g_mkey[(size_t)NREL * N_NODES * NHEAD];
__device__ float         g_z   [(size_t)NREL * N_NODES * NHEAD];
__device__ float         g_e   [(size_t)NREL * NEDGE   * NHEAD];  // scores, then a
// CSR scratch
__device__ unsigned g_deg[NKEY];
__device__ unsigned g_off[NKEY];
__device__ unsigned g_cur[NKEY];
__device__ unsigned g_blk[NBLK];
__device__ int      g_eid[NE_TOT];

// monotone float<->uint encoding so atomicMax(uint) == float max
__device__ __forceinline__ unsigned enc_f(float f) {
    unsigned b = __float_as_uint(f);
    return (b & 0x80000000u) ? ~b : (b | 0x80000000u);
}
__device__ __forceinline__ float dec_f(unsigned k) {
    unsigned b = (k & 0x80000000u) ? (k ^ 0x80000000u) : ~k;
    return __uint_as_float(b);
}

// ---------------- 1. init (z, mkey, deg only — agg no longer needs zeroing) -
__global__ void init_kernel() {
    int i      = blockIdx.x * blockDim.x + threadIdx.x;
    int stride = gridDim.x * blockDim.x;
    const int nh = NREL * N_NODES * NHEAD;
    for (int j = i; j < nh; j += stride) { g_z[j] = 0.f; g_mkey[j] = 0u; }
    for (int j = i; j < NKEY; j += stride) g_deg[j] = 0u;
}

// ---------------- 1b. split x into bf16 hi/lo -------------------------------
__global__ void split_x_kernel(const float* __restrict__ x) {
    int i = blockIdx.x * blockDim.x + threadIdx.x;
    const int total4 = N_NODES * IN_FEAT / 4;
    if (i >= total4) return;
    float4 v = reinterpret_cast<const float4*>(x)[i];
    __nv_bfloat16 h[4], l[4];
    float vv[4] = {v.x, v.y, v.z, v.w};
#pragma unroll
    for (int j = 0; j < 4; j++) {
        h[j] = __float2bfloat16(vv[j]);
        l[j] = __float2bfloat16(vv[j] - __bfloat162float(h[j]));
    }
    *reinterpret_cast<uint2*>(&g_xbh[(size_t)i * 4]) = *reinterpret_cast<uint2*>(h);
    *reinterpret_cast<uint2*>(&g_xbl[(size_t)i * 4]) = *reinterpret_cast<uint2*>(l);
}

// ---------------- 1c. transpose + split W into bf16 hi/lo -------------------
__global__ void split_w_kernel(const float* __restrict__ W) {
    int i = blockIdx.x * blockDim.x + threadIdx.x;
    if (i >= NREL * IN_FEAT * OUTF) return;
    int n = i & 255;
    int k = (i >> 8) & 255;
    int r = i >> 16;
    float w = W[((size_t)r * IN_FEAT + k) * OUTF + n];
    __nv_bfloat16 h = __float2bfloat16(w);
    __nv_bfloat16 l = __float2bfloat16(w - __bfloat162float(h));
    size_t o = ((size_t)r * OUTF + n) * IN_FEAT + k;
    g_wbh[o] = h;
    g_wbl[o] = l;
}

// ---------------- CSR build --------------------------------------------------
__global__ void hist_kernel(const int* __restrict__ dst) {
    int i = blockIdx.x * blockDim.x + threadIdx.x;
    if (i >= NE_TOT) return;
    int r = i / NEDGE;
    int d = dst[i];
    if ((unsigned)d >= N_NODES) return;
    atomicAdd(&g_deg[r * N_NODES + d], 1u);
}

__global__ __launch_bounds__(1024) void scan1_kernel() {
    __shared__ unsigned s[1024];
    int t = threadIdx.x;
    int i = blockIdx.x * 1024 + t;
    unsigned v = (i < NKEY) ? g_deg[i] : 0u;
    s[t] = v;
    __syncthreads();
#pragma unroll
    for (int o = 1; o < 1024; o <<= 1) {
        unsigned u = (t >= o) ? s[t - o] : 0u;
        __syncthreads();
        s[t] += u;
        __syncthreads();
    }
    if (i < NKEY) g_off[i] = s[t] - v;         // within-block exclusive
    if (t == 1023) g_blk[blockIdx.x] = s[1023];
}

__global__ __launch_bounds__(512) void scan2_kernel() {   // one block
    __shared__ unsigned s[512];
    int t = threadIdx.x;
    unsigned v = (t < NBLK) ? g_blk[t] : 0u;
    s[t] = v;
    __syncthreads();
#pragma unroll
    for (int o = 1; o < 512; o <<= 1) {
        unsigned u = (t >= o) ? s[t - o] : 0u;
        __syncthreads();
        s[t] += u;
        __syncthreads();
    }
    if (t < NBLK) g_blk[t] = s[t] - v;         // exclusive block offsets
}

__global__ void scan3_kernel() {
    int i = blockIdx.x * blockDim.x + threadIdx.x;
    if (i >= NKEY) return;
    unsigned o = g_off[i] + g_blk[i >> 10];
    g_off[i] = o;
    g_cur[i] = o;
}

__global__ void scatter_kernel(const int* __restrict__ dst) {
    int i = blockIdx.x * blockDim.x + threadIdx.x;
    if (i >= NE_TOT) return;
    int r = i / NEDGE;
    int d = dst[i];
    if ((unsigned)d >= N_NODES) return;
    unsigned pos = atomicAdd(&g_cur[r * N_NODES + d], 1u);
    g_eid[pos] = i;
}

// ---------------- 2. tensor GEMM via wmma (bf16 split, 3 mma) ---------------
#define GBM 128
#define GBN 128
#define GBK 32
#define SSTRIDE 40

__global__ __launch_bounds__(256, 2) void gemm_wmma_kernel() {
    __shared__ __nv_bfloat16 Ah[GBM * SSTRIDE];
    __shared__ __nv_bfloat16 Al[GBM * SSTRIDE];
    __shared__ __nv_bfloat16 Bh[GBN * SSTRIDE];
    __shared__ __nv_bfloat16 Bl[GBN * SSTRIDE];

    const int tid  = threadIdx.x;
    const int wid  = tid >> 5;
    const int lane = tid & 31;
    const int wm   = wid >> 2;
    const int wn   = wid & 3;
    const int r    = blockIdx.z;
    const int row0 = blockIdx.x * GBM;
    const int col0 = blockIdx.y * GBN;

    const __nv_bfloat16* wbh = g_wbh + (size_t)r * OUTF * IN_FEAT;
    const __nv_bfloat16* wbl = g_wbl + (size_t)r * OUTF * IN_FEAT;

    wmma::fragment<wmma::accumulator, 16, 16, 16, float> acc[4][2];
#pragma unroll
    for (int mt = 0; mt < 4; mt++)
#pragma unroll
        for (int nt = 0; nt < 2; nt++) wmma::fill_fragment(acc[mt][nt], 0.0f);

    for (int kt = 0; kt < IN_FEAT; kt += GBK) {
#pragma unroll
        for (int it = 0; it < 2; it++) {
            int slot = tid + it * 256;
            int m    = slot >> 2;
            int k8   = slot & 3;
            int grow = row0 + m;
            uint4 vh = make_uint4(0u, 0u, 0u, 0u), vl = vh;
            if (grow < N_NODES) {
                size_t go = (size_t)grow * IN_FEAT + kt + k8 * 8;
                vh = *reinterpret_cast<const uint4*>(&g_xbh[go]);
                vl = *reinterpret_cast<const uint4*>(&g_xbl[go]);
            }
            *reinterpret_cast<uint4*>(&Ah[m * SSTRIDE + k8 * 8]) = vh;
            *reinterpret_cast<uint4*>(&Al[m * SSTRIDE + k8 * 8]) = vl;
        }
#pragma unroll
        for (int it = 0; it < 2; it++) {
            int slot = tid + it * 256;
            int n    = slot >> 2;
            int k8   = slot & 3;
            size_t go = (size_t)(col0 + n) * IN_FEAT + kt + k8 * 8;
            uint4 vh = *reinterpret_cast<const uint4*>(&wbh[go]);
            uint4 vl = *reinterpret_cast<const uint4*>(&wbl[go]);
            *reinterpret_cast<uint4*>(&Bh[n * SSTRIDE + k8 * 8]) = vh;
            *reinterpret_cast<uint4*>(&Bl[n * SSTRIDE + k8 * 8]) = vl;
        }
        __syncthreads();

#pragma unroll
        for (int k16 = 0; k16 < GBK; k16 += 16) {
            wmma::fragment<wmma::matrix_b, 16, 16, 16, __nv_bfloat16,
                           wmma::col_major> b_h[2], b_l[2];
#pragma unroll
            for (int nt = 0; nt < 2; nt++) {
                wmma::load_matrix_sync(b_h[nt], &Bh[(wn * 32 + nt * 16) * SSTRIDE + k16], SSTRIDE);
                wmma::load_matrix_sync(b_l[nt], &Bl[(wn * 32 + nt * 16) * SSTRIDE + k16], SSTRIDE);
            }
#pragma unroll
            for (int mt = 0; mt < 4; mt++) {
                wmma::fragment<wmma::matrix_a, 16, 16, 16, __nv_bfloat16,
                               wmma::row_major> a_h, a_l;
                wmma::load_matrix_sync(a_h, &Ah[(wm * 64 + mt * 16) * SSTRIDE + k16], SSTRIDE);
                wmma::load_matrix_sync(a_l, &Al[(wm * 64 + mt * 16) * SSTRIDE + k16], SSTRIDE);
#pragma unroll
                for (int nt = 0; nt < 2; nt++) {
                    wmma::mma_sync(acc[mt][nt], a_h, b_h[nt], acc[mt][nt]);
                    wmma::mma_sync(acc[mt][nt], a_h, b_l[nt], acc[mt][nt]);
                    wmma::mma_sync(acc[mt][nt], a_l, b_h[nt], acc[mt][nt]);
                }
            }
        }
        __syncthreads();
    }

    float* C = g_feat + (size_t)r * N_NODES * OUTF;
    if (row0 + GBM <= N_NODES) {
#pragma unroll
        for (int mt = 0; mt < 4; mt++)
#pragma unroll
            for (int nt = 0; nt < 2; nt++) {
                int row = row0 + wm * 64 + mt * 16;
                int col = col0 + wn * 32 + nt * 16;
                wmma::store_matrix_sync(&C[(size_t)row * OUTF + col],
                                        acc[mt][nt], OUTF, wmma::mem_row_major);
            }
    } else {
        float* scr = reinterpret_cast<float*>(Ah) + wid * 256;
#pragma unroll
        for (int mt = 0; mt < 4; mt++)
#pragma unroll
            for (int nt = 0; nt < 2; nt++) {
                wmma::store_matrix_sync(scr, acc[mt][nt], 16, wmma::mem_row_major);
                __syncwarp();
                int rr = lane >> 1;
                int cc = (lane & 1) * 8;
                int grow = row0 + wm * 64 + mt * 16 + rr;
                if (grow < N_NODES) {
                    float* cp = &C[(size_t)grow * OUTF + col0 + wn * 32 + nt * 16 + cc];
                    const float* sp = &scr[rr * 16 + cc];
#pragma unroll
                    for (int j = 0; j < 8; j++) cp[j] = sp[j];
                }
                __syncwarp();
            }
    }
}

// ---------------- 3. attention dots el/er ----------------------------------
__global__ void attn_kernel(const float* __restrict__ attn_l,
                            const float* __restrict__ attn_r) {
    int gw   = (blockIdx.x * blockDim.x + threadIdx.x) >> 5;
    int lane = threadIdx.x & 31;
    const int total = NREL * N_NODES * NHEAD;
    if (gw >= total) return;
    int h = gw % NHEAD;
    int n = (gw / NHEAD) % N_NODES;
    int r = gw / (NHEAD * N_NODES);
    const float* f = g_feat + ((size_t)r * N_NODES + n) * OUTF + h * DH;
    const float* al = attn_l + (r * NHEAD + h) * DH;
    const float* ar = attn_r + (r * NHEAD + h) * DH;
    float v0 = f[lane], v1 = f[lane + 32];
    float sl = v0 * al[lane] + v1 * al[lane + 32];
    float sr = v0 * ar[lane] + v1 * ar[lane + 32];
#pragma unroll
    for (int o = 16; o > 0; o >>= 1) {
        sl += __shfl_xor_sync(0xffffffffu, sl, o);
        sr += __shfl_xor_sync(0xffffffffu, sr, o);
    }
    if (lane == 0) { g_el[gw] = sl; g_er[gw] = sr; }
}

// ---------------- 4. edge scores + segment max ------------------------------
__global__ void edge1_kernel(const int* __restrict__ src,
                             const int* __restrict__ dst) {
    int i = blockIdx.x * blockDim.x + threadIdx.x;
    if (i >= NE_TOT) return;
    int r = i / NEDGE;
    int s = src[i];
    int d = dst[i];
    if ((unsigned)s >= N_NODES || (unsigned)d >= N_NODES) return;
    float4 l4 = *reinterpret_cast<const float4*>(&g_el[((size_t)r * N_NODES + s) * NHEAD]);
    float4 r4 = *reinterpret_cast<const float4*>(&g_er[((size_t)r * N_NODES + d) * NHEAD]);
    float ev[4] = {l4.x + r4.x, l4.y + r4.y, l4.z + r4.z, l4.w + r4.w};
#pragma unroll
    for (int h = 0; h < 4; h++) ev[h] = (ev[h] > 0.f) ? ev[h] : NEG_SLOPE * ev[h];
    *reinterpret_cast<float4*>(&g_e[(size_t)i * NHEAD]) =
        make_float4(ev[0], ev[1], ev[2], ev[3]);
    unsigned* mk = &g_mkey[((size_t)r * N_NODES + d) * NHEAD];
#pragma unroll
    for (int h = 0; h < 4; h++) atomicMax(&mk[h], enc_f(ev[h]));
}

// ---------------- 5. exp + segment sum --------------------------------------
__global__ void edge2_kernel(const int* __restrict__ dst) {
    int i = blockIdx.x * blockDim.x + threadIdx.x;
    if (i >= NE_TOT) return;
    int r = i / NEDGE;
    int d = dst[i];
    if ((unsigned)d >= N_NODES) return;
    size_t nb = ((size_t)r * N_NODES + d) * NHEAD;
    float4 ev = *reinterpret_cast<const float4*>(&g_e[(size_t)i * NHEAD]);
    uint4  mk = *reinterpret_cast<const uint4*>(&g_mkey[nb]);
    float a0 = __expf(ev.x - dec_f(mk.x));
    float a1 = __expf(ev.y - dec_f(mk.y));
    float a2 = __expf(ev.z - dec_f(mk.z));
    float a3 = __expf(ev.w - dec_f(mk.w));
    *reinterpret_cast<float4*>(&g_e[(size_t)i * NHEAD]) = make_float4(a0, a1, a2, a3);
    atomicAdd(&g_z[nb + 0], a0);
    atomicAdd(&g_z[nb + 1], a1);
    atomicAdd(&g_z[nb + 2], a2);
    atomicAdd(&g_z[nb + 3], a3);
}

// ---------------- 6. CSR aggregation: warp per (rel, dst) -------------------
__global__ void agg_csr_kernel(const int* __restrict__ src) {
    int w    = (blockIdx.x * blockDim.x + threadIdx.x) >> 5;
    int lane = threadIdx.x & 31;
    if (w >= NKEY) return;
    const int r = w / N_NODES;
    const int h = lane >> 3;                       // head for this lane's cols
    const unsigned off = g_off[w];
    const unsigned deg = g_deg[w];

    float zh = fmaxf(g_z[(size_t)w * NHEAD + h], 1e-9f);
    float4 acc0 = make_float4(0.f, 0.f, 0.f, 0.f);
    float4 acc1 = make_float4(0.f, 0.f, 0.f, 0.f);

    const float* featR = g_feat + (size_t)r * N_NODES * OUTF;

    for (unsigned base = 0; base < deg; base += 32) {
        int cnt = (int)(deg - base < 32u ? deg - base : 32u);
        int   sj = 0;
        float4 a4 = make_float4(0.f, 0.f, 0.f, 0.f);
        if (lane < cnt) {
            int e = g_eid[off + base + lane];
            sj = src[e];
            a4 = *reinterpret_cast<const float4*>(&g_e[(size_t)e * NHEAD]);
        }
        for (int j = 0; j < cnt; j++) {
            int   s  = __shfl_sync(0xffffffffu, sj, j);
            float b0 = __shfl_sync(0xffffffffu, a4.x, j);
            float b1 = __shfl_sync(0xffffffffu, a4.y, j);
            float b2 = __shfl_sync(0xffffffffu, a4.z, j);
            float b3 = __shfl_sync(0xffffffffu, a4.w, j);
            float alpha = ((h == 0) ? b0 : (h == 1) ? b1 : (h == 2) ? b2 : b3) / zh;
            if ((unsigned)s >= N_NODES) continue;   // defensive
            const float4* fs = reinterpret_cast<const float4*>(
                &featR[(size_t)s * OUTF]);
            float4 f0 = fs[lane * 2];
            float4 f1 = fs[lane * 2 + 1];
            acc0.x += alpha * f0.x; acc0.y += alpha * f0.y;
            acc0.z += alpha * f0.z; acc0.w += alpha * f0.w;
            acc1.x += alpha * f1.x; acc1.y += alpha * f1.y;
            acc1.z += alpha * f1.z; acc1.w += alpha * f1.w;
        }
    }
    float4* ad = reinterpret_cast<float4*>(&g_agg[(size_t)w * OUTF]);
    ad[lane * 2]     = acc0;
    ad[lane * 2 + 1] = acc1;
}

// ---------------- 7. combine relations + final relu -------------------------
__global__ void final_kernel(const float* __restrict__ bias, float* __restrict__ out) {
    int i = blockIdx.x * blockDim.x + threadIdx.x;
    const int total4 = N_NODES * OUTF / 4;
    if (i >= total4) return;
    int c4 = i & 63;
    int n  = i >> 6;
    float4 acc = make_float4(0.f, 0.f, 0.f, 0.f);
#pragma unroll
    for (int r = 0; r < NREL; r++) {
        float4 g = *reinterpret_cast<const float4*>(
            &g_agg[((size_t)r * N_NODES + n) * OUTF + c4 * 4]);
        float4 b = *reinterpret_cast<const float4*>(&bias[r * OUTF + c4 * 4]);
        acc.x += fmaxf(g.x + b.x, 0.f);
        acc.y += fmaxf(g.y + b.y, 0.f);
        acc.z += fmaxf(g.z + b.z, 0.f);
        acc.w += fmaxf(g.w + b.w, 0.f);
    }
    acc.x = fmaxf(acc.x, 0.f);
    acc.y = fmaxf(acc.y, 0.f);
    acc.z = fmaxf(acc.z, 0.f);
    acc.w = fmaxf(acc.w, 0.f);
    reinterpret_cast<float4*>(out)[i] = acc;
}

// ---------------- launch -----------------------------------------------------
extern "C" void kernel_launch(void* const* d_in, const int* in_sizes, int n_in,
                              void* d_out, int out_size) {
    (void)in_sizes; (void)n_in; (void)out_size;
    const float* x      = (const float*)d_in[0];
    const float* W      = (const float*)d_in[1];
    const float* attn_l = (const float*)d_in[2];
    const float* attn_r = (const float*)d_in[3];
    const float* bias   = (const float*)d_in[4];
    const int*   src    = (const int*)d_in[5];
    const int*   dst    = (const int*)d_in[6];
    float*       out    = (float*)d_out;

    init_kernel<<<512, 256>>>();
    split_x_kernel<<<(N_NODES * IN_FEAT / 4 + 255) / 256, 256>>>(x);
    split_w_kernel<<<(NREL * IN_FEAT * OUTF + 255) / 256, 256>>>(W);

    // CSR build (needs only dst)
    hist_kernel<<<(NE_TOT + 255) / 256, 256>>>(dst);
    scan1_kernel<<<NBLK, 1024>>>();
    scan2_kernel<<<1, 512>>>();
    scan3_kernel<<<(NKEY + 255) / 256, 256>>>();
    scatter_kernel<<<(NE_TOT + 255) / 256, 256>>>(dst);

    dim3 gg((N_NODES + GBM - 1) / GBM, OUTF / GBN, NREL);
    gemm_wmma_kernel<<<gg, 256>>>();

    {
        long long warps = (long long)NREL * N_NODES * NHEAD;
        int blocks = (int)((warps * 32 + 255) / 256);
        attn_kernel<<<blocks, 256>>>(attn_l, attn_r);
    }

    edge1_kernel<<<(NE_TOT + 255) / 256, 256>>>(src, dst);
    edge2_kernel<<<(NE_TOT + 255) / 256, 256>>>(dst);

    {
        long long thr = (long long)NKEY * 32;
        int blocks = (int)((thr + 255) / 256);
        agg_csr_kernel<<<blocks, 256>>>(src);
    }

    final_kernel<<<(N_NODES * OUTF / 4 + 255) / 256, 256>>>(bias, out);
}